// round 14
// baseline (speedup 1.0000x reference)
#include <cuda_runtime.h>
#include <math.h>
#include <stdint.h>

#define BB 4
#define LL 4096
#define CC 1024
#define NHH 16
#define CSS 16
#define HFF 64
#define HF4 256
#define NCC 256
#define MROWS (BB*LL)   // 16384
#define XSZ (BB*NHH*NCC*CSS*HFF)

// ---------------- device scratch -----------------
__device__ float g_X[3*XSZ];                 // [0]=XC, [1]=XB, [2]=XA (split layout)
__device__ float g_coef[BB*NHH*NCC*CSS];
__device__ float g_Z2b[(size_t)MROWS*CC];
__device__ float g_hsr[(size_t)MROWS*CC];
__device__ float g_WT[4][CC*CC];

// ---------------- helpers -----------------
__device__ __forceinline__ float to_tf32(float x){
    uint32_t u; asm("cvt.rna.tf32.f32 %0, %1;" : "=r"(u) : "f"(x));
    return __uint_as_float(u);
}
__device__ __forceinline__ uint32_t f2tf(float x){
    uint32_t u; asm("cvt.rna.tf32.f32 %0, %1;" : "=r"(u) : "f"(x));
    return u;
}
__device__ __forceinline__ void splitf(float v, uint32_t& h, uint32_t& l){
    h = f2tf(v);
    l = f2tf(v - __uint_as_float(h));
}
__device__ __forceinline__ float2 sp(float v){
    uint32_t h,l; splitf(v,h,l);
    return make_float2(__uint_as_float(h), __uint_as_float(l));
}
__device__ __forceinline__ uint32_t fu(float x){ return __float_as_uint(x); }
__device__ __forceinline__ void ldsm4(uint32_t* r, uint32_t addr){
    asm volatile("ldmatrix.sync.aligned.m8n8.x4.shared.b16 {%0,%1,%2,%3}, [%4];"
        : "=r"(r[0]),"=r"(r[1]),"=r"(r[2]),"=r"(r[3]) : "r"(addr));
}
__device__ __forceinline__ void mma_tf32(float* c, const uint32_t* a, uint32_t b0, uint32_t b1){
    asm volatile("mma.sync.aligned.m16n8k8.row.col.f32.tf32.tf32.f32 "
        "{%0,%1,%2,%3},{%4,%5,%6,%7},{%8,%9},{%0,%1,%2,%3};"
        : "+f"(c[0]),"+f"(c[1]),"+f"(c[2]),"+f"(c[3])
        : "r"(a[0]),"r"(a[1]),"r"(a[2]),"r"(a[3]),"r"(b0),"r"(b1));
}
__device__ __forceinline__ void mma3(float* c, const uint32_t* ah, const uint32_t* al,
                                     const uint32_t* bh, const uint32_t* bl){
    mma_tf32(c, ah, bh[0], bh[1]);
    mma_tf32(c, ah, bl[0], bl[1]);
    mma_tf32(c, al, bh[0], bh[1]);
}
// raw split-at-consume loader (W1 only)
__device__ __forceinline__ void ldBf(const float* S, int ld, int k0, int n0, int lane,
                                     uint32_t* bh, uint32_t* bl){
    int g = lane >> 2, tg = lane & 3;
    splitf(S[(k0+tg)*ld + n0+g],   bh[0], bl[0]);
    splitf(S[(k0+tg+4)*ld + n0+g], bh[1], bl[1]);
}
// twin-array loaders (pre-split)
__device__ __forceinline__ void ldAf2(const float* Sh, const float* Sl, int ld, int k0,
                                      int lane, uint32_t* ah, uint32_t* al){
    int g = lane >> 2, tg = lane & 3;
    ah[0]=fu(Sh[g*ld + k0+tg]);       al[0]=fu(Sl[g*ld + k0+tg]);
    ah[1]=fu(Sh[(g+8)*ld + k0+tg]);   al[1]=fu(Sl[(g+8)*ld + k0+tg]);
    ah[2]=fu(Sh[g*ld + k0+tg+4]);     al[2]=fu(Sl[g*ld + k0+tg+4]);
    ah[3]=fu(Sh[(g+8)*ld + k0+tg+4]); al[3]=fu(Sl[(g+8)*ld + k0+tg+4]);
}
__device__ __forceinline__ void ldAfT2(const float* Sh, const float* Sl, int ld, int m0,
                                       int k0, int lane, uint32_t* ah, uint32_t* al){
    int g = lane >> 2, tg = lane & 3;
    ah[0]=fu(Sh[(k0+tg)*ld + m0+g]);     al[0]=fu(Sl[(k0+tg)*ld + m0+g]);
    ah[1]=fu(Sh[(k0+tg)*ld + m0+g+8]);   al[1]=fu(Sl[(k0+tg)*ld + m0+g+8]);
    ah[2]=fu(Sh[(k0+tg+4)*ld + m0+g]);   al[2]=fu(Sl[(k0+tg+4)*ld + m0+g]);
    ah[3]=fu(Sh[(k0+tg+4)*ld + m0+g+8]); al[3]=fu(Sl[(k0+tg+4)*ld + m0+g+8]);
}
__device__ __forceinline__ void ldBf2(const float* Sh, const float* Sl, int ld, int k0,
                                      int n0, int lane, uint32_t* bh, uint32_t* bl){
    int g = lane >> 2, tg = lane & 3;
    bh[0]=fu(Sh[(k0+tg)*ld + n0+g]);   bl[0]=fu(Sl[(k0+tg)*ld + n0+g]);
    bh[1]=fu(Sh[(k0+tg+4)*ld + n0+g]); bl[1]=fu(Sl[(k0+tg+4)*ld + n0+g]);
}
__device__ __forceinline__ void ldBfT2(const float* Sh, const float* Sl, int ld, int k0,
                                       int n0, int lane, uint32_t* bh, uint32_t* bl){
    int g = lane >> 2, tg = lane & 3;
    bh[0]=fu(Sh[(n0+g)*ld + k0+tg]);   bl[0]=fu(Sl[(n0+g)*ld + k0+tg]);
    bh[1]=fu(Sh[(n0+g)*ld + k0+tg+4]); bl[1]=fu(Sl[(n0+g)*ld + k0+tg+4]);
}

// ---------------- cluster helpers -----------------
#define CLUSTER_SYNC() do{ \
    asm volatile("barrier.cluster.arrive.aligned;" ::: "memory"); \
    asm volatile("barrier.cluster.wait.aligned;"   ::: "memory"); }while(0)

__device__ __forceinline__ uint32_t mapa_u32(uint32_t laddr, uint32_t rank){
    uint32_t ra; asm("mapa.shared::cluster.u32 %0, %1, %2;" : "=r"(ra) : "r"(laddr), "r"(rank));
    return ra;
}
__device__ __forceinline__ float2 peer_f2(uint32_t laddr, uint32_t peer){
    uint32_t ra = mapa_u32(laddr, peer);
    float2 v;
    asm volatile("ld.shared::cluster.v2.f32 {%0,%1}, [%2];"
        : "=f"(v.x),"=f"(v.y) : "r"(ra));
    return v;
}
__device__ __forceinline__ float peer_f1(uint32_t laddr, uint32_t peer){
    uint32_t ra = mapa_u32(laddr, peer);
    float v;
    asm volatile("ld.shared::cluster.f32 %0, [%1];" : "=f"(v) : "r"(ra));
    return v;
}

// ---------------- prep kernels -----------------
__global__ void __launch_bounds__(256) round_kernel(const float* __restrict__ in,
                                                    float* __restrict__ out){
    size_t i = (size_t)blockIdx.x*256 + threadIdx.x;
    float4 v = ((const float4*)in)[i];
    ((float4*)out)[i] = make_float4(to_tf32(v.x), to_tf32(v.y), to_tf32(v.z), to_tf32(v.w));
}
__global__ void __launch_bounds__(256) transpose3i_kernel(const float* __restrict__ Wq,
                                                          const float* __restrict__ Wk,
                                                          const float* __restrict__ Wv,
                                                          float* __restrict__ out,
                                                          const float* __restrict__ hs,
                                                          const float* __restrict__ ilw,
                                                          const float* __restrict__ ilb){
    if (blockIdx.z < 3){
        __shared__ float tile[32][33];
        const float* in = (blockIdx.z==0) ? Wq : (blockIdx.z==1) ? Wk : Wv;
        float* o = out + (size_t)blockIdx.z*CC*CC;
        int bx = blockIdx.x*32, by = blockIdx.y*32;
        int tx = threadIdx.x & 31, ty = threadIdx.x >> 5;
        for (int r = ty; r < 32; r += 8)
            tile[r][tx] = in[(size_t)(by+r)*CC + bx + tx];
        __syncthreads();
        for (int r = ty; r < 32; r += 8)
            o[(size_t)(bx+r)*CC + by + tx] = to_tf32(tile[tx][r]);
    } else {
        int blk = blockIdx.y*32 + blockIdx.x;
        int h = threadIdx.x & 15, rloc = threadIdx.x >> 4;
        int row = blk*16 + rloc;
        const float* hp = hs + (size_t)row*CC;
        float a0=0.f,a1=0.f,a2=0.f,a3=0.f;
        for (int k=0;k<CC;k+=4){
            float4 x = *(const float4*)(hp + k);
            a0 += x.x*ilw[(k+0)*NHH+h];
            a1 += x.y*ilw[(k+1)*NHH+h];
            a2 += x.z*ilw[(k+2)*NHH+h];
            a3 += x.w*ilw[(k+3)*NHH+h];
        }
        float acc = (a0+a1)+(a2+a3) + ilb[h];
        float sig = 1.f/(1.f+expf(-acc));
        int b = row>>12, l = row&4095, n = l>>4, s = l&15;
        g_coef[((size_t)(b*NHH+h)*NCC+n)*CSS+s] = sig*(1.f/(float)(s+1))*(1.f/(float)HFF);
    }
}
__global__ void __launch_bounds__(256) transpose_kernel(const float* __restrict__ in,
                                                        float* __restrict__ out){
    __shared__ float tile[32][33];
    int bx = blockIdx.x*32, by = blockIdx.y*32;
    int tx = threadIdx.x & 31, ty = threadIdx.x >> 5;
    for (int r = ty; r < 32; r += 8)
        tile[r][tx] = in[(size_t)(by+r)*CC + bx + tx];
    __syncthreads();
    for (int r = ty; r < 32; r += 8)
        out[(size_t)(bx+r)*CC + by + tx] = to_tf32(tile[tx][r]);
}

// ---------------- tf32 GEMM (unchanged) --------------------------------------
#define GPAD 36
template<int SPLIT>
__global__ void __launch_bounds__(256) gemm_tf32(const float* __restrict__ A,
                                                 const float* __restrict__ BT,
                                                 float* __restrict__ out)
{
    __shared__ float As[128*GPAD];
    __shared__ float Bs[128*GPAD];
    const int t = threadIdx.x, lane = t & 31, warp = t >> 5;
    const int wm = warp >> 1, wn = warp & 1;
    const int bm = blockIdx.y, bn = blockIdx.x;

    float acc[2][8][4];
#pragma unroll
    for (int i=0;i<2;i++)
#pragma unroll
        for (int j=0;j<8;j++)
#pragma unroll
            for (int q=0;q<4;q++) acc[i][j][q]=0.f;

    const uint32_t As_u = (uint32_t)__cvta_generic_to_shared(As);
    const uint32_t Bs_u = (uint32_t)__cvta_generic_to_shared(Bs);
    uint32_t a_addr[2], b_addr[4];
#pragma unroll
    for (int mf=0; mf<2; mf++){
        int row = wm*32 + mf*16 + (lane & 15);
        a_addr[mf] = As_u + (uint32_t)(row*GPAD + (lane>>4)*4)*4u;
    }
#pragma unroll
    for (int nf2=0; nf2<4; nf2++){
        int nr = wn*64 + nf2*16 + (lane & 7) + ((lane>>4)&1)*8;
        b_addr[nf2] = Bs_u + (uint32_t)(nr*GPAD + ((lane>>3)&1)*4)*4u;
    }

    const float* Ab  = A  + (size_t)(bm*128)*CC;
    const float* BTb = BT + (size_t)(bn*128)*CC;
    const int row = t >> 3, k4 = (t & 7)*4;

    float4 ar[4], br[4];
#pragma unroll
    for (int i=0;i<4;i++){
        int r = row + i*32;
        ar[i] = *(const float4*)(Ab  + (size_t)r*CC + k4);
        br[i] = *(const float4*)(BTb + (size_t)r*CC + k4);
    }

    for (int it=0; it<32; it++){
        __syncthreads();
#pragma unroll
        for (int i=0;i<4;i++){
            int r = row + i*32;
            *(float4*)&As[r*GPAD + k4] = ar[i];
            *(float4*)&Bs[r*GPAD + k4] = br[i];
        }
        __syncthreads();
        if (it < 31){
            const int kb = (it+1)*32;
#pragma unroll
            for (int i=0;i<4;i++){
                int r = row + i*32;
                ar[i] = *(const float4*)(Ab  + (size_t)r*CC + kb + k4);
                br[i] = *(const float4*)(BTb + (size_t)r*CC + kb + k4);
            }
        }
#pragma unroll
        for (int s8=0; s8<4; s8++){
            uint32_t a[2][4], bf[4][4];
            ldsm4(a[0], a_addr[0] + s8*32);
            ldsm4(a[1], a_addr[1] + s8*32);
            ldsm4(bf[0], b_addr[0] + s8*32);
            ldsm4(bf[1], b_addr[1] + s8*32);
            ldsm4(bf[2], b_addr[2] + s8*32);
            ldsm4(bf[3], b_addr[3] + s8*32);
#pragma unroll
            for (int nf=0; nf<8; nf++){
                uint32_t b0 = bf[nf>>1][(nf&1)*2], b1 = bf[nf>>1][(nf&1)*2+1];
                mma_tf32(acc[0][nf], a[0], b0, b1);
                mma_tf32(acc[1][nf], a[1], b0, b1);
            }
        }
    }

#pragma unroll
    for (int mf=0; mf<2; mf++){
#pragma unroll
        for (int nf=0; nf<8; nf++){
            int r = bm*128 + wm*32 + mf*16 + (lane>>2);
            int c = bn*128 + wn*64 + nf*8 + (lane&3)*2;
#pragma unroll
            for (int half=0; half<2; half++){
                int rr = r + half*8;
                float2 v = make_float2(acc[mf][nf][half*2], acc[mf][nf][half*2+1]);
                if (SPLIT){
                    int proj = c >> 10, cc = c & 1023;
                    int b = rr >> 12, l = rr & 4095;
                    int n = l >> 4, s = l & 15;
                    int h = cc >> 6, f = cc & 63;
                    size_t idx = (size_t)proj*XSZ +
                                 ((((size_t)(b*NHH + h)*NCC + n)*CSS + s)*HFF + f);
                    *(float2*)(out + idx) = v;
                } else {
                    *(float2*)(out + (size_t)rr*CC + c) = v;
                }
            }
        }
    }
}

// ---------------- TTT scan: 2-CTA cluster, twin caches, 512 threads ----------
#define D_W1    0                        // raw 64x132
#define D_W2H   (D_W1 + 64*132)
#define D_W2L   (D_W2H + 128*72)
#define D_XA    (D_W2L + 128*72)         // raw 16x68
#define D_XBH   (D_XA + 16*68)
#define D_XBL   (D_XBH + 16*68)
#define D_XCH   (D_XBL + 16*68)
#define D_XCL   (D_XCH + 16*68)
#define D_Z1H   (D_XCL + 16*68)          // 16x132
#define D_Z1L   (D_Z1H + 16*132)
#define D_Z1BH  (D_Z1L + 16*132)
#define D_Z1BL  (D_Z1BH + 16*132)
#define D_G1H   (D_Z1BL + 16*132)
#define D_G1L   (D_G1H + 16*132)
#define D_G2H   (D_G1L + 16*132)         // 16x72
#define D_G2L   (D_G2H + 16*72)
#define D_Z2P   (D_G2L + 16*72)          // raw 16x72 (DSMEM)
#define D_Z2BP  (D_Z2P + 16*72)          // raw 16x72 (DSMEM)
#define D_A1MH  (D_Z2BP + 16*72)         // 16x20
#define D_A1ML  (D_A1MH + 16*20)
#define D_A2MH  (D_A1ML + 16*20)
#define D_A2ML  (D_A2MH + 16*20)
#define D_A2P   (D_A2ML + 16*20)         // raw 16x20 (DSMEM)
#define D_ST    (D_A2P + 16*20)          // 8x16x18
#define D_CO    (D_ST + 8*16*18)
#define SCAN_SMEM_FLOATS (D_CO + 16)
#define SCAN_SMEM_BYTES  (SCAN_SMEM_FLOATS*4)

__global__ void __launch_bounds__(512,1) __cluster_dims__(2,1,1)
scan_kernel(const float* __restrict__ W1g, const float* __restrict__ W2g)
{
    extern __shared__ float sm[];
    float* sW1   = sm + D_W1;
    float* sW2h  = sm + D_W2H;
    float* sW2l  = sm + D_W2L;
    float* sXA   = sm + D_XA;
    float* sXBh  = sm + D_XBH;
    float* sXBl  = sm + D_XBL;
    float* sXCh  = sm + D_XCH;
    float* sXCl  = sm + D_XCL;
    float* sZ1h  = sm + D_Z1H;
    float* sZ1l  = sm + D_Z1L;
    float* sZ1bh = sm + D_Z1BH;
    float* sZ1bl = sm + D_Z1BL;
    float* sG1h  = sm + D_G1H;
    float* sG1l  = sm + D_G1L;
    float* sG2h  = sm + D_G2H;
    float* sG2l  = sm + D_G2L;
    float* sZ2p  = sm + D_Z2P;
    float* sZ2bp = sm + D_Z2BP;
    float* sA1mh = sm + D_A1MH;
    float* sA1ml = sm + D_A1ML;
    float* sA2mh = sm + D_A2MH;
    float* sA2ml = sm + D_A2ML;
    float* sA2p  = sm + D_A2P;
    float* sSt   = sm + D_ST;
    float* sCo   = sm + D_CO;

    const int t = threadIdx.x;
    const int lane = t & 31, w = t >> 5;           // w in [0,16)
    const int g = lane >> 2, tg = lane & 3;
    uint32_t rank; asm("mov.u32 %0, %%cluster_ctarank;" : "=r"(rank));
    const uint32_t peer = rank ^ 1u;
    const int bh = blockIdx.x >> 1;
    const int b  = bh >> 4, h = bh & 15;
    const uint32_t smb = (uint32_t)__cvta_generic_to_shared(sm);

    const float* w1p = W1g + (size_t)h*HFF*HF4;
    for (int i = t; i < HFF*128; i += 512)
        sW1[(i>>7)*132 + (i&127)] = w1p[(size_t)(i>>7)*HF4 + rank*128 + (i&127)];
    const float* w2p = W2g + (size_t)h*HF4*HFF;
    for (int i = t; i < 128*HFF; i += 512){
        int k = i>>6, f = i&63;
        float2 v = sp(w2p[(size_t)(rank*128 + k)*HFF + f]);
        sW2h[k*72 + f] = v.x;
        sW2l[k*72 + f] = v.y;
    }

    const size_t cbase = (size_t)bh * (NCC*CSS*HFF);
    const float* gXC = g_X;
    const float* gXB = g_X + XSZ;
    const float* gXA = g_X + 2*(size_t)XSZ;

    for (int n = 0; n < NCC; n++) {
        // ---- chunk load: 512 threads x float2 ----
        {
            int e = t*2, s = e >> 6, f = e & 63;
            const float* base = (const float*)0;
            float2 va = *(const float2*)(gXA + cbase + (size_t)n*1024 + e);
            float2 vb = *(const float2*)(gXB + cbase + (size_t)n*1024 + e);
            float2 vc = *(const float2*)(gXC + cbase + (size_t)n*1024 + e);
            (void)base;
            *(float2*)(sXA + s*68 + f) = va;
            float2 b0=sp(vb.x), b1=sp(vb.y);
            *(float2*)&sXBh[s*68 + f] = make_float2(b0.x, b1.x);
            *(float2*)&sXBl[s*68 + f] = make_float2(b0.y, b1.y);
            float2 c0=sp(vc.x), c1_=sp(vc.y);
            *(float2*)&sXCh[s*68 + f] = make_float2(c0.x, c1_.x);
            *(float2*)&sXCl[s*68 + f] = make_float2(c0.y, c1_.y);
            if (t < 16) sCo[t] = g_coef[(size_t)bh*(NCC*CSS) + n*CSS + t];
        }
        __syncthreads();

        // ---- P1: Z1loc = XB@W1loc ; Ploc = XC@W1loc. 16 warps x 8 cols ----
        {
            const int n0 = w*8;
            float aZ[4] = {0.f,0.f,0.f,0.f}, aP[4] = {0.f,0.f,0.f,0.f};
#pragma unroll
            for (int ks=0; ks<8; ks++){
                int k0 = ks*8;
                uint32_t aBh[4],aBl[4],aCh[4],aCl[4],bhf[2],blf[2];
                ldAf2(sXBh, sXBl, 68, k0, lane, aBh, aBl);
                ldAf2(sXCh, sXCl, 68, k0, lane, aCh, aCl);
                ldBf(sW1, 132, k0, n0, lane, bhf, blf);
                mma3(aZ, aBh, aBl, bhf, blf);
                mma3(aP, aCh, aCl, bhf, blf);
            }
            int col = n0 + 2*tg;
            float2 z0=sp(aZ[0]), z1=sp(aZ[1]), z2=sp(aZ[2]), z3=sp(aZ[3]);
            *(float2*)&sZ1h[g*132 + col]     = make_float2(z0.x, z1.x);
            *(float2*)&sZ1l[g*132 + col]     = make_float2(z0.y, z1.y);
            *(float2*)&sZ1h[(g+8)*132 + col] = make_float2(z2.x, z3.x);
            *(float2*)&sZ1l[(g+8)*132 + col] = make_float2(z2.y, z3.y);
            float2 p0=sp(aP[0]), p1=sp(aP[1]), p2=sp(aP[2]), p3=sp(aP[3]);
            *(float2*)&sZ1bh[g*132 + col]     = make_float2(p0.x, p1.x);
            *(float2*)&sZ1bl[g*132 + col]     = make_float2(p0.y, p1.y);
            *(float2*)&sZ1bh[(g+8)*132 + col] = make_float2(p2.x, p3.x);
            *(float2*)&sZ1bl[(g+8)*132 + col] = make_float2(p2.y, p3.y);
        }
        __syncthreads();

        // ---- P2: warps 0-7: Z2 partial ; warps 8-9: A1m ----
        if (w < 8){
            const int n0 = w*8;
            float acc[4] = {0.f,0.f,0.f,0.f};
#pragma unroll 4
            for (int ks=0; ks<16; ks++){
                int k0 = ks*8;
                uint32_t ah[4],al[4],bhf[2],blf[2];
                ldAf2(sZ1h, sZ1l, 132, k0, lane, ah, al);
                ldBf2(sW2h, sW2l, 72, k0, n0, lane, bhf, blf);
                mma3(acc, ah, al, bhf, blf);
            }
            int col = n0 + 2*tg;
            *(float2*)&sZ2p[g*72 + col]     = make_float2(acc[0], acc[1]);
            *(float2*)&sZ2p[(g+8)*72 + col] = make_float2(acc[2], acc[3]);
        } else if (w < 10){
            const int an0 = (w-8)*8;
            float a1[4] = {0.f,0.f,0.f,0.f};
#pragma unroll
            for (int ks=0; ks<8; ks++){
                int k0 = ks*8;
                uint32_t ah[4],al[4],bhf[2],blf[2];
                ldAf2(sXCh, sXCl, 68, k0, lane, ah, al);
                ldBfT2(sXBh, sXBl, 68, k0, an0, lane, bhf, blf);
                mma3(a1, ah, al, bhf, blf);
            }
            int u0 = an0 + 2*tg;
            int s0 = g, s1 = g+8;
            float2 q;
            q = (u0   <= s0) ? sp(-sCo[s0]*a1[0]) : make_float2(0.f,0.f);
            sA1mh[s0*20 + u0] = q.x;   sA1ml[s0*20 + u0] = q.y;
            q = (u0+1 <= s0) ? sp(-sCo[s0]*a1[1]) : make_float2(0.f,0.f);
            sA1mh[s0*20 + u0+1] = q.x; sA1ml[s0*20 + u0+1] = q.y;
            q = (u0   <= s1) ? sp(-sCo[s1]*a1[2]) : make_float2(0.f,0.f);
            sA1mh[s1*20 + u0] = q.x;   sA1ml[s1*20 + u0] = q.y;
            q = (u0+1 <= s1) ? sp(-sCo[s1]*a1[3]) : make_float2(0.f,0.f);
            sA1mh[s1*20 + u0+1] = q.x; sA1ml[s1*20 + u0+1] = q.y;
        }
        CLUSTER_SYNC();

        // ---- g2 = Z2p_own + Z2p_peer - XA -> twin stores (512 thr x 2) ----
        {
            int row = t >> 5, c2 = (t & 31)*2;
            float2 own = *(float2*)&sZ2p[row*72 + c2];
            float2 pv  = peer_f2(smb + (uint32_t)(D_Z2P + row*72 + c2)*4u, peer);
            float2 xa  = *(float2*)&sXA[row*68 + c2];
            float2 g0 = sp(own.x+pv.x-xa.x), g1_ = sp(own.y+pv.y-xa.y);
            *(float2*)&sG2h[row*72 + c2] = make_float2(g0.x, g1_.x);
            *(float2*)&sG2l[row*72 + c2] = make_float2(g0.y, g1_.y);
        }
        __syncthreads();

        // ---- P3: g1loc = g2 @ W2loc^T. 16 warps x 8 cols ----
        {
            const int n0 = w*8;
            float accG[4] = {0.f,0.f,0.f,0.f};
#pragma unroll
            for (int ks=0; ks<8; ks++){
                int k0 = ks*8;
                uint32_t ah[4],al[4],bhf[2],blf[2];
                ldAf2(sG2h, sG2l, 72, k0, lane, ah, al);
                ldBfT2(sW2h, sW2l, 72, k0, n0, lane, bhf, blf);
                mma3(accG, ah, al, bhf, blf);
            }
            int col = n0 + 2*tg;
            float2 q0=sp(accG[0]), q1=sp(accG[1]), q2=sp(accG[2]), q3=sp(accG[3]);
            *(float2*)&sG1h[g*132 + col]     = make_float2(q0.x, q1.x);
            *(float2*)&sG1l[g*132 + col]     = make_float2(q0.y, q1.y);
            *(float2*)&sG1h[(g+8)*132 + col] = make_float2(q2.x, q3.x);
            *(float2*)&sG1l[(g+8)*132 + col] = make_float2(q2.y, q3.y);
        }
        __syncthreads();

        // ---- P4: Z1b += A1m@g1loc (16 warps x 8 cols) ; W1 update (16 x 16x32) ----
        {
            const int n0 = w*8;
            float c1[4] = {0.f,0.f,0.f,0.f};
#pragma unroll
            for (int ks=0; ks<2; ks++){
                int k0 = ks*8;
                uint32_t ah[4],al[4],bhf[2],blf[2];
                ldAf2(sA1mh, sA1ml, 20, k0, lane, ah, al);
                ldBf2(sG1h, sG1l, 132, k0, n0, lane, bhf, blf);
                mma3(c1, ah, al, bhf, blf);
            }
            int col = n0 + 2*tg;
            float2 h0 = *(float2*)&sZ1bh[g*132 + col];
            float2 l0 = *(float2*)&sZ1bl[g*132 + col];
            float2 h1 = *(float2*)&sZ1bh[(g+8)*132 + col];
            float2 l1 = *(float2*)&sZ1bl[(g+8)*132 + col];
            float2 s00 = sp(h0.x + l0.x + c1[0]);
            float2 s01 = sp(h0.y + l0.y + c1[1]);
            float2 s10 = sp(h1.x + l1.x + c1[2]);
            float2 s11 = sp(h1.y + l1.y + c1[3]);
            *(float2*)&sZ1bh[g*132 + col]     = make_float2(s00.x, s01.x);
            *(float2*)&sZ1bl[g*132 + col]     = make_float2(s00.y, s01.y);
            *(float2*)&sZ1bh[(g+8)*132 + col] = make_float2(s10.x, s11.x);
            *(float2*)&sZ1bl[(g+8)*132 + col] = make_float2(s10.y, s11.y);

            const float cl = sCo[15];
            const int m0 = (w>>2)*16, nbase = (w&3)*32;
            float wa[4][4];
#pragma unroll
            for (int i=0;i<4;i++)
#pragma unroll
                for (int q=0;q<4;q++) wa[i][q]=0.f;
#pragma unroll
            for (int ks=0; ks<2; ks++){
                int k0 = ks*8;
                uint32_t ah[4],al[4];
                ldAfT2(sXBh, sXBl, 68, m0, k0, lane, ah, al);
#pragma unroll
                for (int nf=0; nf<4; nf++){
                    uint32_t bhf[2], blf[2];
                    ldBf2(sG1h, sG1l, 132, k0, nbase + nf*8, lane, bhf, blf);
                    mma3(wa[nf], ah, al, bhf, blf);
                }
            }
#pragma unroll
            for (int nf=0; nf<4; nf++){
                int colw = nbase + nf*8 + 2*tg;
                float2 v0 = *(float2*)&sW1[(m0+g)*132 + colw];
                float2 v1 = *(float2*)&sW1[(m0+g+8)*132 + colw];
                v0.x -= cl*wa[nf][0]; v0.y -= cl*wa[nf][1];
                v1.x -= cl*wa[nf][2]; v1.y -= cl*wa[nf][3];
                *(float2*)&sW1[(m0+g)*132 + colw]   = v0;
                *(float2*)&sW1[(m0+g+8)*132 + colw] = v1;
            }
        }
        __syncthreads();

        // ---- P5: warps 0-7: Z2b partial ; warps 8-15: A2 K-split partials ----
        float zacc[4] = {0.f,0.f,0.f,0.f};
        if (w < 8){
            const int n0 = w*8;
#pragma unroll 4
            for (int ks=0; ks<16; ks++){
                int k0 = ks*8;
                uint32_t ah[4],al[4],bhf[2],blf[2];
                ldAf2(sZ1bh, sZ1bl, 132, k0, lane, ah, al);
                ldBf2(sW2h, sW2l, 72, k0, n0, lane, bhf, blf);
                mma3(zacc, ah, al, bhf, blf);
            }
            int col = n0 + 2*tg;
            *(float2*)&sZ2bp[g*72 + col]     = make_float2(zacc[0], zacc[1]);
            *(float2*)&sZ2bp[(g+8)*72 + col] = make_float2(zacc[2], zacc[3]);
        } else {
            const int ws = w - 8;
            float pa[2][4];
#pragma unroll
            for (int i=0;i<2;i++)
#pragma unroll
                for (int q=0;q<4;q++) pa[i][q]=0.f;
            const int kb = ws*16;
#pragma unroll
            for (int ks=0; ks<2; ks++){
                int k0 = kb + ks*8;
                uint32_t ah[4],al[4];
                ldAf2(sZ1bh, sZ1bl, 132, k0, lane, ah, al);
#pragma unroll
                for (int nf=0; nf<2; nf++){
                    uint32_t bhf[2], blf[2];
                    ldBfT2(sZ1h, sZ1l, 132, k0, nf*8, lane, bhf, blf);
                    mma3(pa[nf], ah, al, bhf, blf);
                }
            }
#pragma unroll
            for (int nf=0; nf<2; nf++){
                int u = nf*8 + 2*tg;
                sSt[ws*288 + g*18 + u]       = pa[nf][0];
                sSt[ws*288 + g*18 + u+1]     = pa[nf][1];
                sSt[ws*288 + (g+8)*18 + u]   = pa[nf][2];
                sSt[ws*288 + (g+8)*18 + u+1] = pa[nf][3];
            }
        }
        __syncthreads();

        // ---- P5r: reduce staged A2 partials -> CTA partial (raw) ----
        if (t < 256){
            int s = t >> 4, u = t & 15;
            float sum = 0.f;
#pragma unroll
            for (int ww=0; ww<8; ww++) sum += sSt[ww*288 + s*18 + u];
            sA2p[s*20 + u] = sum;
        }
        CLUSTER_SYNC();

        // ---- A2m twins = split(-co*tril(A2_own + A2_peer)) ----
        if (t < 256){
            int s = t >> 4, u = t & 15;
            float pv = peer_f1(smb + (uint32_t)(D_A2P + s*20 + u)*4u, peer);
            float sum = sA2p[s*20 + u] + pv;
            float2 q = (u <= s) ? sp(-sCo[s]*sum) : make_float2(0.f,0.f);
            sA2mh[s*20 + u] = q.x;
            sA2ml[s*20 + u] = q.y;
        }
        __syncthreads();

        // ---- P6: warps 0-7: corr2 + store ; all: W2 update (16 x 16x32) ----
        if (w < 8){
            const int n0 = w*8;
#pragma unroll
            for (int ks=0; ks<2; ks++){
                int k0 = ks*8;
                uint32_t ah[4],al[4],bhf[2],blf[2];
                ldAf2(sA2mh, sA2ml, 20, k0, lane, ah, al);
                ldBf2(sG2h, sG2l, 72, k0, n0, lane, bhf, blf);
                mma3(zacc, ah, al, bhf, blf);
            }
            int srow = rank ? (g+8) : g;
            float2 pv = peer_f2(smb + (uint32_t)(D_Z2BP + srow*72 + n0 + 2*tg)*4u, peer);
            float2 ownv = rank ? make_float2(zacc[2], zacc[3])
                               : make_float2(zacc[0], zacc[1]);
            int col = h*HFF + n0 + 2*tg;
            size_t ridx = (size_t)(b*LL + n*CSS + srow)*CC + col;
            *(float2*)&g_Z2b[ridx] =
                make_float2(to_tf32(ownv.x + pv.x), to_tf32(ownv.y + pv.y));
        }
        {
            const float cl = sCo[15];
            const int m0 = (w>>1)*16, nfb = (w&1)*4;
            float wa[4][4];
#pragma unroll
            for (int i=0;i<4;i++)
#pragma unroll
                for (int q=0;q<4;q++) wa[i][q]=0.f;
#pragma unroll
            for (int ks=0; ks<2; ks++){
                int k0 = ks*8;
                uint32_t ah[4],al[4];
                ldAfT2(sZ1h, sZ1l, 132, m0, k0, lane, ah, al);
#pragma unroll
                for (int nf=0; nf<4; nf++){
                    uint32_t bhf[2], blf[2];
                    ldBf2(sG2h, sG2l, 72, k0, (nfb+nf)*8, lane, bhf, blf);
                    mma3(wa[nf], ah, al, bhf, blf);
                }
            }
#pragma unroll
            for (int nf=0; nf<4; nf++){
                int col = (nfb+nf)*8 + 2*tg;
                float2 h0 = *(float2*)&sW2h[(m0+g)*72 + col];
                float2 l0 = *(float2*)&sW2l[(m0+g)*72 + col];
                float2 h1 = *(float2*)&sW2h[(m0+g+8)*72 + col];
                float2 l1 = *(float2*)&sW2l[(m0+g+8)*72 + col];
                float2 sa = sp(h0.x + l0.x - cl*wa[nf][0]);
                float2 sb = sp(h0.y + l0.y - cl*wa[nf][1]);
                float2 sc = sp(h1.x + l1.x - cl*wa[nf][2]);
                float2 sd = sp(h1.y + l1.y - cl*wa[nf][3]);
                *(float2*)&sW2h[(m0+g)*72 + col]   = make_float2(sa.x, sb.x);
                *(float2*)&sW2l[(m0+g)*72 + col]   = make_float2(sa.y, sb.y);
                *(float2*)&sW2h[(m0+g+8)*72 + col] = make_float2(sc.x, sd.x);
                *(float2*)&sW2l[(m0+g+8)*72 + col] = make_float2(sc.y, sd.y);
            }
        }
        __syncthreads();
    }
    CLUSTER_SYNC();
}

// ---------------- launch -----------------
extern "C" void kernel_launch(void* const* d_in, const int* in_sizes, int n_in,
                              void* d_out, int out_size)
{
    const float* hs  = (const float*)d_in[0];
    const float* Wq  = (const float*)d_in[1];
    const float* Wk  = (const float*)d_in[2];
    const float* Wv  = (const float*)d_in[3];
    const float* Wo  = (const float*)d_in[4];
    const float* ilw = (const float*)d_in[5];
    const float* ilb = (const float*)d_in[6];
    const float* W1  = (const float*)d_in[7];
    const float* W2  = (const float*)d_in[8];
    float* out = (float*)d_out;

    cudaFuncSetAttribute(scan_kernel, cudaFuncAttributeMaxDynamicSharedMemorySize,
                         SCAN_SMEM_BYTES);

    void *pX, *pZ2b, *pHsr, *pWT;
    cudaGetSymbolAddress(&pX, g_X);
    cudaGetSymbolAddress(&pZ2b, g_Z2b);
    cudaGetSymbolAddress(&pHsr, g_hsr);
    cudaGetSymbolAddress(&pWT, g_WT);
    float* hsr = (float*)pHsr;
    float* WT  = (float*)pWT;

    // launch 1: round
    round_kernel<<<(size_t)MROWS*CC/4/256, 256>>>(hs, hsr);
    // launch 2: transposes + ilr fused
    transpose3i_kernel<<<dim3(32,32,4), 256>>>(Wq, Wk, Wv, WT, hs, ilw, ilb);
    // launch 3: fused QKV GEMM
    dim3 gq(3*CC/128, MROWS/128);
    gemm_tf32<1><<<gq, 256>>>(hsr, WT, (float*)pX);
    // launch 4: scan (ncu capture slot)
    scan_kernel<<<BB*NHH*2, 512, SCAN_SMEM_BYTES>>>(W1, W2);
    // launch 5-6: Wo transpose + output GEMM
    transpose_kernel<<<dim3(32,32), 256>>>(Wo, WT + 3*(size_t)CC*CC);
    dim3 go(CC/128, MROWS/128);
    gemm_tf32<0><<<go, 256>>>((const float*)pZ2b, WT + 3*(size_t)CC*CC, out);
}

// round 15
// speedup vs baseline: 1.1187x; 1.1187x over previous
#include <cuda_runtime.h>
#include <math.h>
#include <stdint.h>

#define BB 4
#define LL 4096
#define CC 1024
#define NHH 16
#define CSS 16
#define HFF 64
#define HF4 256
#define NCC 256
#define MROWS (BB*LL)   // 16384
#define XSZ (BB*NHH*NCC*CSS*HFF)

// ---------------- device scratch -----------------
__device__ float g_X[3*XSZ];                 // [0]=XC, [1]=XB, [2]=XA (split layout)
__device__ float g_coef[BB*NHH*NCC*CSS];
__device__ float g_Z2b[(size_t)MROWS*CC];
__device__ float g_hsr[(size_t)MROWS*CC];
__device__ float g_WT[4][CC*CC];

// ---------------- helpers -----------------
__device__ __forceinline__ float to_tf32(float x){
    uint32_t u; asm("cvt.rna.tf32.f32 %0, %1;" : "=r"(u) : "f"(x));
    return __uint_as_float(u);
}
__device__ __forceinline__ uint32_t f2tf(float x){
    uint32_t u; asm("cvt.rna.tf32.f32 %0, %1;" : "=r"(u) : "f"(x));
    return u;
}
__device__ __forceinline__ void splitf(float v, uint32_t& h, uint32_t& l){
    h = f2tf(v);
    l = f2tf(v - __uint_as_float(h));
}
__device__ __forceinline__ float2 sp(float v){
    uint32_t h,l; splitf(v,h,l);
    return make_float2(__uint_as_float(h), __uint_as_float(l));
}
__device__ __forceinline__ uint32_t fu(float x){ return __float_as_uint(x); }
__device__ __forceinline__ void ldsm4(uint32_t* r, uint32_t addr){
    asm volatile("ldmatrix.sync.aligned.m8n8.x4.shared.b16 {%0,%1,%2,%3}, [%4];"
        : "=r"(r[0]),"=r"(r[1]),"=r"(r[2]),"=r"(r[3]) : "r"(addr));
}
__device__ __forceinline__ void mma_tf32(float* c, const uint32_t* a, uint32_t b0, uint32_t b1){
    asm volatile("mma.sync.aligned.m16n8k8.row.col.f32.tf32.tf32.f32 "
        "{%0,%1,%2,%3},{%4,%5,%6,%7},{%8,%9},{%0,%1,%2,%3};"
        : "+f"(c[0]),"+f"(c[1]),"+f"(c[2]),"+f"(c[3])
        : "r"(a[0]),"r"(a[1]),"r"(a[2]),"r"(a[3]),"r"(b0),"r"(b1));
}
__device__ __forceinline__ void mma3(float* c, const uint32_t* ah, const uint32_t* al,
                                     const uint32_t* bh, const uint32_t* bl){
    mma_tf32(c, ah, bh[0], bh[1]);
    mma_tf32(c, ah, bl[0], bl[1]);
    mma_tf32(c, al, bh[0], bh[1]);
}
// raw split-at-consume loader (W1 only)
__device__ __forceinline__ void ldBf(const float* S, int ld, int k0, int n0, int lane,
                                     uint32_t* bh, uint32_t* bl){
    int g = lane >> 2, tg = lane & 3;
    splitf(S[(k0+tg)*ld + n0+g],   bh[0], bl[0]);
    splitf(S[(k0+tg+4)*ld + n0+g], bh[1], bl[1]);
}
// twin-array loaders (pre-split)
__device__ __forceinline__ void ldAf2(const float* Sh, const float* Sl, int ld, int k0,
                                      int lane, uint32_t* ah, uint32_t* al){
    int g = lane >> 2, tg = lane & 3;
    ah[0]=fu(Sh[g*ld + k0+tg]);       al[0]=fu(Sl[g*ld + k0+tg]);
    ah[1]=fu(Sh[(g+8)*ld + k0+tg]);   al[1]=fu(Sl[(g+8)*ld + k0+tg]);
    ah[2]=fu(Sh[g*ld + k0+tg+4]);     al[2]=fu(Sl[g*ld + k0+tg+4]);
    ah[3]=fu(Sh[(g+8)*ld + k0+tg+4]); al[3]=fu(Sl[(g+8)*ld + k0+tg+4]);
}
__device__ __forceinline__ void ldAfT2(const float* Sh, const float* Sl, int ld, int m0,
                                       int k0, int lane, uint32_t* ah, uint32_t* al){
    int g = lane >> 2, tg = lane & 3;
    ah[0]=fu(Sh[(k0+tg)*ld + m0+g]);     al[0]=fu(Sl[(k0+tg)*ld + m0+g]);
    ah[1]=fu(Sh[(k0+tg)*ld + m0+g+8]);   al[1]=fu(Sl[(k0+tg)*ld + m0+g+8]);
    ah[2]=fu(Sh[(k0+tg+4)*ld + m0+g]);   al[2]=fu(Sl[(k0+tg+4)*ld + m0+g]);
    ah[3]=fu(Sh[(k0+tg+4)*ld + m0+g+8]); al[3]=fu(Sl[(k0+tg+4)*ld + m0+g+8]);
}
__device__ __forceinline__ void ldBf2(const float* Sh, const float* Sl, int ld, int k0,
                                      int n0, int lane, uint32_t* bh, uint32_t* bl){
    int g = lane >> 2, tg = lane & 3;
    bh[0]=fu(Sh[(k0+tg)*ld + n0+g]);   bl[0]=fu(Sl[(k0+tg)*ld + n0+g]);
    bh[1]=fu(Sh[(k0+tg+4)*ld + n0+g]); bl[1]=fu(Sl[(k0+tg+4)*ld + n0+g]);
}
__device__ __forceinline__ void ldBfT2(const float* Sh, const float* Sl, int ld, int k0,
                                       int n0, int lane, uint32_t* bh, uint32_t* bl){
    int g = lane >> 2, tg = lane & 3;
    bh[0]=fu(Sh[(n0+g)*ld + k0+tg]);   bl[0]=fu(Sl[(n0+g)*ld + k0+tg]);
    bh[1]=fu(Sh[(n0+g)*ld + k0+tg+4]); bl[1]=fu(Sl[(n0+g)*ld + k0+tg+4]);
}

// ---------------- cluster helpers -----------------
#define CLUSTER_SYNC() do{ \
    asm volatile("barrier.cluster.arrive.aligned;" ::: "memory"); \
    asm volatile("barrier.cluster.wait.aligned;"   ::: "memory"); }while(0)

__device__ __forceinline__ uint32_t mapa_u32(uint32_t laddr, uint32_t rank){
    uint32_t ra; asm("mapa.shared::cluster.u32 %0, %1, %2;" : "=r"(ra) : "r"(laddr), "r"(rank));
    return ra;
}
__device__ __forceinline__ float4 peer_f4(uint32_t laddr, uint32_t peer){
    uint32_t ra = mapa_u32(laddr, peer);
    float4 v;
    asm volatile("ld.shared::cluster.v4.f32 {%0,%1,%2,%3}, [%4];"
        : "=f"(v.x),"=f"(v.y),"=f"(v.z),"=f"(v.w) : "r"(ra));
    return v;
}
__device__ __forceinline__ float2 peer_f2(uint32_t laddr, uint32_t peer){
    uint32_t ra = mapa_u32(laddr, peer);
    float2 v;
    asm volatile("ld.shared::cluster.v2.f32 {%0,%1}, [%2];"
        : "=f"(v.x),"=f"(v.y) : "r"(ra));
    return v;
}
__device__ __forceinline__ float peer_f1(uint32_t laddr, uint32_t peer){
    uint32_t ra = mapa_u32(laddr, peer);
    float v;
    asm volatile("ld.shared::cluster.f32 %0, [%1];" : "=f"(v) : "r"(ra));
    return v;
}

// ---------------- prep kernels -----------------
__global__ void __launch_bounds__(256) round_kernel(const float* __restrict__ in,
                                                    float* __restrict__ out){
    size_t i = (size_t)blockIdx.x*256 + threadIdx.x;
    float4 v = ((const float4*)in)[i];
    ((float4*)out)[i] = make_float4(to_tf32(v.x), to_tf32(v.y), to_tf32(v.z), to_tf32(v.w));
}
__global__ void __launch_bounds__(256) transpose3i_kernel(const float* __restrict__ Wq,
                                                          const float* __restrict__ Wk,
                                                          const float* __restrict__ Wv,
                                                          float* __restrict__ out,
                                                          const float* __restrict__ hs,
                                                          const float* __restrict__ ilw,
                                                          const float* __restrict__ ilb){
    if (blockIdx.z < 3){
        __shared__ float tile[32][33];
        const float* in = (blockIdx.z==0) ? Wq : (blockIdx.z==1) ? Wk : Wv;
        float* o = out + (size_t)blockIdx.z*CC*CC;
        int bx = blockIdx.x*32, by = blockIdx.y*32;
        int tx = threadIdx.x & 31, ty = threadIdx.x >> 5;
        for (int r = ty; r < 32; r += 8)
            tile[r][tx] = in[(size_t)(by+r)*CC + bx + tx];
        __syncthreads();
        for (int r = ty; r < 32; r += 8)
            o[(size_t)(bx+r)*CC + by + tx] = to_tf32(tile[tx][r]);
    } else {
        int blk = blockIdx.y*32 + blockIdx.x;
        int h = threadIdx.x & 15, rloc = threadIdx.x >> 4;
        int row = blk*16 + rloc;
        const float* hp = hs + (size_t)row*CC;
        float a0=0.f,a1=0.f,a2=0.f,a3=0.f;
        for (int k=0;k<CC;k+=4){
            float4 x = *(const float4*)(hp + k);
            a0 += x.x*ilw[(k+0)*NHH+h];
            a1 += x.y*ilw[(k+1)*NHH+h];
            a2 += x.z*ilw[(k+2)*NHH+h];
            a3 += x.w*ilw[(k+3)*NHH+h];
        }
        float acc = (a0+a1)+(a2+a3) + ilb[h];
        float sig = 1.f/(1.f+expf(-acc));
        int b = row>>12, l = row&4095, n = l>>4, s = l&15;
        g_coef[((size_t)(b*NHH+h)*NCC+n)*CSS+s] = sig*(1.f/(float)(s+1))*(1.f/(float)HFF);
    }
}
__global__ void __launch_bounds__(256) transpose_kernel(const float* __restrict__ in,
                                                        float* __restrict__ out){
    __shared__ float tile[32][33];
    int bx = blockIdx.x*32, by = blockIdx.y*32;
    int tx = threadIdx.x & 31, ty = threadIdx.x >> 5;
    for (int r = ty; r < 32; r += 8)
        tile[r][tx] = in[(size_t)(by+r)*CC + bx + tx];
    __syncthreads();
    for (int r = ty; r < 32; r += 8)
        out[(size_t)(bx+r)*CC + by + tx] = to_tf32(tile[tx][r]);
}

// ---------------- tf32 GEMM (unchanged) --------------------------------------
#define GPAD 36
template<int SPLIT>
__global__ void __launch_bounds__(256) gemm_tf32(const float* __restrict__ A,
                                                 const float* __restrict__ BT,
                                                 float* __restrict__ out)
{
    __shared__ float As[128*GPAD];
    __shared__ float Bs[128*GPAD];
    const int t = threadIdx.x, lane = t & 31, warp = t >> 5;
    const int wm = warp >> 1, wn = warp & 1;
    const int bm = blockIdx.y, bn = blockIdx.x;

    float acc[2][8][4];
#pragma unroll
    for (int i=0;i<2;i++)
#pragma unroll
        for (int j=0;j<8;j++)
#pragma unroll
            for (int q=0;q<4;q++) acc[i][j][q]=0.f;

    const uint32_t As_u = (uint32_t)__cvta_generic_to_shared(As);
    const uint32_t Bs_u = (uint32_t)__cvta_generic_to_shared(Bs);
    uint32_t a_addr[2], b_addr[4];
#pragma unroll
    for (int mf=0; mf<2; mf++){
        int row = wm*32 + mf*16 + (lane & 15);
        a_addr[mf] = As_u + (uint32_t)(row*GPAD + (lane>>4)*4)*4u;
    }
#pragma unroll
    for (int nf2=0; nf2<4; nf2++){
        int nr = wn*64 + nf2*16 + (lane & 7) + ((lane>>4)&1)*8;
        b_addr[nf2] = Bs_u + (uint32_t)(nr*GPAD + ((lane>>3)&1)*4)*4u;
    }

    const float* Ab  = A  + (size_t)(bm*128)*CC;
    const float* BTb = BT + (size_t)(bn*128)*CC;
    const int row = t >> 3, k4 = (t & 7)*4;

    float4 ar[4], br[4];
#pragma unroll
    for (int i=0;i<4;i++){
        int r = row + i*32;
        ar[i] = *(const float4*)(Ab  + (size_t)r*CC + k4);
        br[i] = *(const float4*)(BTb + (size_t)r*CC + k4);
    }

    for (int it=0; it<32; it++){
        __syncthreads();
#pragma unroll
        for (int i=0;i<4;i++){
            int r = row + i*32;
            *(float4*)&As[r*GPAD + k4] = ar[i];
            *(float4*)&Bs[r*GPAD + k4] = br[i];
        }
        __syncthreads();
        if (it < 31){
            const int kb = (it+1)*32;
#pragma unroll
            for (int i=0;i<4;i++){
                int r = row + i*32;
                ar[i] = *(const float4*)(Ab  + (size_t)r*CC + kb + k4);
                br[i] = *(const float4*)(BTb + (size_t)r*CC + kb + k4);
            }
        }
#pragma unroll
        for (int s8=0; s8<4; s8++){
            uint32_t a[2][4], bf[4][4];
            ldsm4(a[0], a_addr[0] + s8*32);
            ldsm4(a[1], a_addr[1] + s8*32);
            ldsm4(bf[0], b_addr[0] + s8*32);
            ldsm4(bf[1], b_addr[1] + s8*32);
            ldsm4(bf[2], b_addr[2] + s8*32);
            ldsm4(bf[3], b_addr[3] + s8*32);
#pragma unroll
            for (int nf=0; nf<8; nf++){
                uint32_t b0 = bf[nf>>1][(nf&1)*2], b1 = bf[nf>>1][(nf&1)*2+1];
                mma_tf32(acc[0][nf], a[0], b0, b1);
                mma_tf32(acc[1][nf], a[1], b0, b1);
            }
        }
    }

#pragma unroll
    for (int mf=0; mf<2; mf++){
#pragma unroll
        for (int nf=0; nf<8; nf++){
            int r = bm*128 + wm*32 + mf*16 + (lane>>2);
            int c = bn*128 + wn*64 + nf*8 + (lane&3)*2;
#pragma unroll
            for (int half=0; half<2; half++){
                int rr = r + half*8;
                float2 v = make_float2(acc[mf][nf][half*2], acc[mf][nf][half*2+1]);
                if (SPLIT){
                    int proj = c >> 10, cc = c & 1023;
                    int b = rr >> 12, l = rr & 4095;
                    int n = l >> 4, s = l & 15;
                    int h = cc >> 6, f = cc & 63;
                    size_t idx = (size_t)proj*XSZ +
                                 ((((size_t)(b*NHH + h)*NCC + n)*CSS + s)*HFF + f);
                    *(float2*)(out + idx) = v;
                } else {
                    *(float2*)(out + (size_t)rr*CC + c) = v;
                }
            }
        }
    }
}

// ---------------- TTT scan: 2-CTA cluster, twin caches, X prefetch -----------
#define D_W1    0                        // raw 64x132
#define D_W2H   (D_W1 + 64*132)
#define D_W2L   (D_W2H + 128*72)
#define D_XA    (D_W2L + 128*72)         // raw 16x68
#define D_XBH   (D_XA + 16*68)
#define D_XBL   (D_XBH + 16*68)
#define D_XCH   (D_XBL + 16*68)
#define D_XCL   (D_XCH + 16*68)
#define D_Z1H   (D_XCL + 16*68)          // 16x132
#define D_Z1L   (D_Z1H + 16*132)
#define D_Z1BH  (D_Z1L + 16*132)
#define D_Z1BL  (D_Z1BH + 16*132)
#define D_G1H   (D_Z1BL + 16*132)
#define D_G1L   (D_G1H + 16*132)
#define D_G2H   (D_G1L + 16*132)         // 16x72
#define D_G2L   (D_G2H + 16*72)
#define D_Z2P   (D_G2L + 16*72)          // raw 16x72 (DSMEM)
#define D_Z2BP  (D_Z2P + 16*72)          // raw 16x72 (DSMEM)
#define D_A1MH  (D_Z2BP + 16*72)         // 16x20
#define D_A1ML  (D_A1MH + 16*20)
#define D_A2MH  (D_A1ML + 16*20)
#define D_A2ML  (D_A2MH + 16*20)
#define D_A2P   (D_A2ML + 16*20)         // raw 16x20 (DSMEM)
#define D_ST    (D_A2P + 16*20)          // 8x16x18
#define D_CO    (D_ST + 8*16*18)
#define SCAN_SMEM_FLOATS (D_CO + 16)
#define SCAN_SMEM_BYTES  (SCAN_SMEM_FLOATS*4)

__global__ void __launch_bounds__(256,1) __cluster_dims__(2,1,1)
scan_kernel(const float* __restrict__ W1g, const float* __restrict__ W2g)
{
    extern __shared__ float sm[];
    float* sW1   = sm + D_W1;
    float* sW2h  = sm + D_W2H;
    float* sW2l  = sm + D_W2L;
    float* sXA   = sm + D_XA;
    float* sXBh  = sm + D_XBH;
    float* sXBl  = sm + D_XBL;
    float* sXCh  = sm + D_XCH;
    float* sXCl  = sm + D_XCL;
    float* sZ1h  = sm + D_Z1H;
    float* sZ1l  = sm + D_Z1L;
    float* sZ1bh = sm + D_Z1BH;
    float* sZ1bl = sm + D_Z1BL;
    float* sG1h  = sm + D_G1H;
    float* sG1l  = sm + D_G1L;
    float* sG2h  = sm + D_G2H;
    float* sG2l  = sm + D_G2L;
    float* sZ2p  = sm + D_Z2P;
    float* sZ2bp = sm + D_Z2BP;
    float* sA1mh = sm + D_A1MH;
    float* sA1ml = sm + D_A1ML;
    float* sA2mh = sm + D_A2MH;
    float* sA2ml = sm + D_A2ML;
    float* sA2p  = sm + D_A2P;
    float* sSt   = sm + D_ST;
    float* sCo   = sm + D_CO;

    const int t = threadIdx.x;
    const int lane = t & 31, w = t >> 5;
    const int g = lane >> 2, tg = lane & 3;
    uint32_t rank; asm("mov.u32 %0, %%cluster_ctarank;" : "=r"(rank));
    const uint32_t peer = rank ^ 1u;
    const int bh = blockIdx.x >> 1;
    const int b  = bh >> 4, h = bh & 15;
    const uint32_t smb = (uint32_t)__cvta_generic_to_shared(sm);

    const float* w1p = W1g + (size_t)h*HFF*HF4;
    for (int i = t; i < HFF*128; i += 256)
        sW1[(i>>7)*132 + (i&127)] = w1p[(size_t)(i>>7)*HF4 + rank*128 + (i&127)];
    const float* w2p = W2g + (size_t)h*HF4*HFF;
    for (int i = t; i < 128*HFF; i += 256){
        int k = i>>6, f = i&63;
        float2 v = sp(w2p[(size_t)(rank*128 + k)*HFF + f]);
        sW2h[k*72 + f] = v.x;
        sW2l[k*72 + f] = v.y;
    }

    const size_t cbase = (size_t)bh * (NCC*CSS*HFF);
    const float* gXC = g_X;
    const float* gXB = g_X + XSZ;
    const float* gXA = g_X + 2*(size_t)XSZ;

    // prefetch chunk 0 into registers
    float4 pfa, pfb, pfc;
    float pfco = 0.f;
    pfa = ((const float4*)(gXA + cbase))[t];
    pfb = ((const float4*)(gXB + cbase))[t];
    pfc = ((const float4*)(gXC + cbase))[t];
    if (t < 16) pfco = g_coef[(size_t)bh*(NCC*CSS) + t];

    for (int n = 0; n < NCC; n++) {
        // ---- store prefetched chunk to smem (split XB/XC) ----
        {
            int e = t*4, s = e >> 6, f = e & 63;
            *(float4*)(sXA + s*68 + f) = pfa;
            float2 b0=sp(pfb.x), b1=sp(pfb.y), b2=sp(pfb.z), b3=sp(pfb.w);
            *(float4*)&sXBh[s*68 + f] = make_float4(b0.x,b1.x,b2.x,b3.x);
            *(float4*)&sXBl[s*68 + f] = make_float4(b0.y,b1.y,b2.y,b3.y);
            float2 c0=sp(pfc.x), c1_=sp(pfc.y), c2=sp(pfc.z), c3=sp(pfc.w);
            *(float4*)&sXCh[s*68 + f] = make_float4(c0.x,c1_.x,c2.x,c3.x);
            *(float4*)&sXCl[s*68 + f] = make_float4(c0.y,c1_.y,c2.y,c3.y);
            if (t < 16) sCo[t] = pfco;
        }
        __syncthreads();
        // ---- issue prefetch for chunk n+1 (completes during phases) ----
        if (n+1 < NCC){
            const size_t off = cbase + (size_t)(n+1)*1024;
            pfa = ((const float4*)(gXA + off))[t];
            pfb = ((const float4*)(gXB + off))[t];
            pfc = ((const float4*)(gXC + off))[t];
            if (t < 16) pfco = g_coef[(size_t)bh*(NCC*CSS) + (n+1)*CSS + t];
        }

        // ---- P1: Z1loc = XB@W1loc ; Ploc = XC@W1loc -> twin stores ----
        {
            const int n0 = w*16;
            float aZ[2][4], aP[2][4];
#pragma unroll
            for (int i=0;i<2;i++)
#pragma unroll
                for (int q=0;q<4;q++){ aZ[i][q]=0.f; aP[i][q]=0.f; }
#pragma unroll
            for (int ks=0; ks<8; ks++){
                int k0 = ks*8;
                uint32_t aBh[4],aBl[4],aCh[4],aCl[4];
                ldAf2(sXBh, sXBl, 68, k0, lane, aBh, aBl);
                ldAf2(sXCh, sXCl, 68, k0, lane, aCh, aCl);
#pragma unroll
                for (int nf=0; nf<2; nf++){
                    uint32_t bhf[2], blf[2];
                    ldBf(sW1, 132, k0, n0+nf*8, lane, bhf, blf);
                    mma3(aZ[nf], aBh, aBl, bhf, blf);
                    mma3(aP[nf], aCh, aCl, bhf, blf);
                }
            }
#pragma unroll
            for (int nf=0; nf<2; nf++){
                int col = n0 + nf*8 + 2*tg;
                float2 z0=sp(aZ[nf][0]), z1=sp(aZ[nf][1]), z2=sp(aZ[nf][2]), z3=sp(aZ[nf][3]);
                *(float2*)&sZ1h[g*132 + col]     = make_float2(z0.x, z1.x);
                *(float2*)&sZ1l[g*132 + col]     = make_float2(z0.y, z1.y);
                *(float2*)&sZ1h[(g+8)*132 + col] = make_float2(z2.x, z3.x);
                *(float2*)&sZ1l[(g+8)*132 + col] = make_float2(z2.y, z3.y);
                float2 p0=sp(aP[nf][0]), p1=sp(aP[nf][1]), p2=sp(aP[nf][2]), p3=sp(aP[nf][3]);
                *(float2*)&sZ1bh[g*132 + col]     = make_float2(p0.x, p1.x);
                *(float2*)&sZ1bl[g*132 + col]     = make_float2(p0.y, p1.y);
                *(float2*)&sZ1bh[(g+8)*132 + col] = make_float2(p2.x, p3.x);
                *(float2*)&sZ1bl[(g+8)*132 + col] = make_float2(p2.y, p3.y);
            }
        }
        __syncthreads();

        // ---- P2: Z2 partial ; warps 0,1: A1m twins ----
        {
            const int n0 = w*8;
            float acc[4] = {0.f,0.f,0.f,0.f};
#pragma unroll 4
            for (int ks=0; ks<16; ks++){
                int k0 = ks*8;
                uint32_t ah[4],al[4],bhf[2],blf[2];
                ldAf2(sZ1h, sZ1l, 132, k0, lane, ah, al);
                ldBf2(sW2h, sW2l, 72, k0, n0, lane, bhf, blf);
                mma3(acc, ah, al, bhf, blf);
            }
            {
                int col = n0 + 2*tg;
                *(float2*)&sZ2p[g*72 + col]     = make_float2(acc[0], acc[1]);
                *(float2*)&sZ2p[(g+8)*72 + col] = make_float2(acc[2], acc[3]);
            }
            if (w < 2){
                const int an0 = w*8;
                float a1[4] = {0.f,0.f,0.f,0.f};
#pragma unroll
                for (int ks=0; ks<8; ks++){
                    int k0 = ks*8;
                    uint32_t ah[4],al[4],bhf[2],blf[2];
                    ldAf2(sXCh, sXCl, 68, k0, lane, ah, al);
                    ldBfT2(sXBh, sXBl, 68, k0, an0, lane, bhf, blf);
                    mma3(a1, ah, al, bhf, blf);
                }
                int u0 = an0 + 2*tg;
                int s0 = g, s1 = g+8;
                float2 q;
                q = (u0   <= s0) ? sp(-sCo[s0]*a1[0]) : make_float2(0.f,0.f);
                sA1mh[s0*20 + u0] = q.x;   sA1ml[s0*20 + u0] = q.y;
                q = (u0+1 <= s0) ? sp(-sCo[s0]*a1[1]) : make_float2(0.f,0.f);
                sA1mh[s0*20 + u0+1] = q.x; sA1ml[s0*20 + u0+1] = q.y;
                q = (u0   <= s1) ? sp(-sCo[s1]*a1[2]) : make_float2(0.f,0.f);
                sA1mh[s1*20 + u0] = q.x;   sA1ml[s1*20 + u0] = q.y;
                q = (u0+1 <= s1) ? sp(-sCo[s1]*a1[3]) : make_float2(0.f,0.f);
                sA1mh[s1*20 + u0+1] = q.x; sA1ml[s1*20 + u0+1] = q.y;
            }
        }
        CLUSTER_SYNC();

        // ---- g2 = Z2p_own + Z2p_peer - XA -> twin stores ----
        {
            int row = t >> 4, c4 = (t & 15)*4;
            float4 own = *(float4*)&sZ2p[row*72 + c4];
            float4 pv  = peer_f4(smb + (uint32_t)(D_Z2P + row*72 + c4)*4u, peer);
            float4 xa  = *(float4*)&sXA[row*68 + c4];
            float2 g0 = sp(own.x+pv.x-xa.x), g1_ = sp(own.y+pv.y-xa.y);
            float2 g2_ = sp(own.z+pv.z-xa.z), g3 = sp(own.w+pv.w-xa.w);
            *(float4*)&sG2h[row*72 + c4] = make_float4(g0.x,g1_.x,g2_.x,g3.x);
            *(float4*)&sG2l[row*72 + c4] = make_float4(g0.y,g1_.y,g2_.y,g3.y);
        }
        __syncthreads();

        // ---- P3: g1loc = g2 @ W2loc^T -> twin stores ----
        {
            const int n0 = w*16;
            float accG[2][4];
#pragma unroll
            for (int i=0;i<2;i++)
#pragma unroll
                for (int q=0;q<4;q++) accG[i][q]=0.f;
#pragma unroll
            for (int ks=0; ks<8; ks++){
                int k0 = ks*8;
                uint32_t ah[4],al[4];
                ldAf2(sG2h, sG2l, 72, k0, lane, ah, al);
#pragma unroll
                for (int nf=0; nf<2; nf++){
                    uint32_t bhf[2], blf[2];
                    ldBfT2(sW2h, sW2l, 72, k0, n0+nf*8, lane, bhf, blf);
                    mma3(accG[nf], ah, al, bhf, blf);
                }
            }
#pragma unroll
            for (int nf=0; nf<2; nf++){
                int col = n0 + nf*8 + 2*tg;
                float2 q0=sp(accG[nf][0]), q1=sp(accG[nf][1]), q2=sp(accG[nf][2]), q3=sp(accG[nf][3]);
                *(float2*)&sG1h[g*132 + col]     = make_float2(q0.x, q1.x);
                *(float2*)&sG1l[g*132 + col]     = make_float2(q0.y, q1.y);
                *(float2*)&sG1h[(g+8)*132 + col] = make_float2(q2.x, q3.x);
                *(float2*)&sG1l[(g+8)*132 + col] = make_float2(q2.y, q3.y);
            }
        }
        __syncthreads();

        // ---- P4: Z1b += A1m@g1loc ; W1 -= cl*(XB^T@g1loc) ----
        {
            const int n0 = w*16;
            float c1[2][4];
#pragma unroll
            for (int i=0;i<2;i++)
#pragma unroll
                for (int q=0;q<4;q++) c1[i][q]=0.f;
#pragma unroll
            for (int ks=0; ks<2; ks++){
                int k0 = ks*8;
                uint32_t ah[4],al[4];
                ldAf2(sA1mh, sA1ml, 20, k0, lane, ah, al);
#pragma unroll
                for (int nf=0; nf<2; nf++){
                    uint32_t bhf[2], blf[2];
                    ldBf2(sG1h, sG1l, 132, k0, n0+nf*8, lane, bhf, blf);
                    mma3(c1[nf], ah, al, bhf, blf);
                }
            }
#pragma unroll
            for (int nf=0; nf<2; nf++){
                int col = n0 + nf*8 + 2*tg;
                float2 h0 = *(float2*)&sZ1bh[g*132 + col];
                float2 l0 = *(float2*)&sZ1bl[g*132 + col];
                float2 h1 = *(float2*)&sZ1bh[(g+8)*132 + col];
                float2 l1 = *(float2*)&sZ1bl[(g+8)*132 + col];
                float2 s00 = sp(h0.x + l0.x + c1[nf][0]);
                float2 s01 = sp(h0.y + l0.y + c1[nf][1]);
                float2 s10 = sp(h1.x + l1.x + c1[nf][2]);
                float2 s11 = sp(h1.y + l1.y + c1[nf][3]);
                *(float2*)&sZ1bh[g*132 + col]     = make_float2(s00.x, s01.x);
                *(float2*)&sZ1bl[g*132 + col]     = make_float2(s00.y, s01.y);
                *(float2*)&sZ1bh[(g+8)*132 + col] = make_float2(s10.x, s11.x);
                *(float2*)&sZ1bl[(g+8)*132 + col] = make_float2(s10.y, s11.y);
            }
            const float cl = sCo[15];
            const int m0 = (w>>1)*16, nbase = (w&1)*64;
            float wa[8][4];
#pragma unroll
            for (int i=0;i<8;i++)
#pragma unroll
                for (int q=0;q<4;q++) wa[i][q]=0.f;
#pragma unroll
            for (int ks=0; ks<2; ks++){
                int k0 = ks*8;
                uint32_t ah[4],al[4];
                ldAfT2(sXBh, sXBl, 68, m0, k0, lane, ah, al);
#pragma unroll
                for (int nf=0; nf<8; nf++){
                    uint32_t bhf[2], blf[2];
                    ldBf2(sG1h, sG1l, 132, k0, nbase + nf*8, lane, bhf, blf);
                    mma3(wa[nf], ah, al, bhf, blf);
                }
            }
#pragma unroll
            for (int nf=0; nf<8; nf++){
                int col = nbase + nf*8 + 2*tg;
                float2 v0 = *(float2*)&sW1[(m0+g)*132 + col];
                float2 v1 = *(float2*)&sW1[(m0+g+8)*132 + col];
                v0.x -= cl*wa[nf][0]; v0.y -= cl*wa[nf][1];
                v1.x -= cl*wa[nf][2]; v1.y -= cl*wa[nf][3];
                *(float2*)&sW1[(m0+g)*132 + col]   = v0;
                *(float2*)&sW1[(m0+g+8)*132 + col] = v1;
            }
        }
        __syncthreads();

        // ---- P5: Z2b partial ; A2 partial ----
        float zacc[4] = {0.f,0.f,0.f,0.f};
        {
            const int n0 = w*8;
#pragma unroll 4
            for (int ks=0; ks<16; ks++){
                int k0 = ks*8;
                uint32_t ah[4],al[4],bhf[2],blf[2];
                ldAf2(sZ1bh, sZ1bl, 132, k0, lane, ah, al);
                ldBf2(sW2h, sW2l, 72, k0, n0, lane, bhf, blf);
                mma3(zacc, ah, al, bhf, blf);
            }
            {
                int col = n0 + 2*tg;
                *(float2*)&sZ2bp[g*72 + col]     = make_float2(zacc[0], zacc[1]);
                *(float2*)&sZ2bp[(g+8)*72 + col] = make_float2(zacc[2], zacc[3]);
            }
            float pa[2][4];
#pragma unroll
            for (int i=0;i<2;i++)
#pragma unroll
                for (int q=0;q<4;q++) pa[i][q]=0.f;
            const int kb = w*16;
#pragma unroll
            for (int ks=0; ks<2; ks++){
                int k0 = kb + ks*8;
                uint32_t ah[4],al[4];
                ldAf2(sZ1bh, sZ1bl, 132, k0, lane, ah, al);
#pragma unroll
                for (int nf=0; nf<2; nf++){
                    uint32_t bhf[2], blf[2];
                    ldBfT2(sZ1h, sZ1l, 132, k0, nf*8, lane, bhf, blf);
                    mma3(pa[nf], ah, al, bhf, blf);
                }
            }
#pragma unroll
            for (int nf=0; nf<2; nf++){
                int u = nf*8 + 2*tg;
                sSt[w*288 + g*18 + u]       = pa[nf][0];
                sSt[w*288 + g*18 + u+1]     = pa[nf][1];
                sSt[w*288 + (g+8)*18 + u]   = pa[nf][2];
                sSt[w*288 + (g+8)*18 + u+1] = pa[nf][3];
            }
        }
        __syncthreads();

        // ---- P5r: reduce staged A2 partials -> CTA partial (raw) ----
        {
            int s = t >> 4, u = t & 15;
            float sum = 0.f;
#pragma unroll
            for (int ww=0; ww<8; ww++) sum += sSt[ww*288 + s*18 + u];
            sA2p[s*20 + u] = sum;
        }
        CLUSTER_SYNC();

        // ---- A2m twins = split(-co*tril(A2_own + A2_peer)) ----
        {
            int s = t >> 4, u = t & 15;
            float pv = peer_f1(smb + (uint32_t)(D_A2P + s*20 + u)*4u, peer);
            float sum = sA2p[s*20 + u] + pv;
            float2 q = (u <= s) ? sp(-sCo[s]*sum) : make_float2(0.f,0.f);
            sA2mh[s*20 + u] = q.x;
            sA2ml[s*20 + u] = q.y;
        }
        __syncthreads();

        // ---- P6: corr2 ; combine + store ; W2 twin update ----
        {
            const int n0 = w*8;
#pragma unroll
            for (int ks=0; ks<2; ks++){
                int k0 = ks*8;
                uint32_t ah[4],al[4],bhf[2],blf[2];
                ldAf2(sA2mh, sA2ml, 20, k0, lane, ah, al);
                ldBf2(sG2h, sG2l, 72, k0, n0, lane, bhf, blf);
                mma3(zacc, ah, al, bhf, blf);
            }
            {
                int srow = rank ? (g+8) : g;
                float2 pv = peer_f2(smb + (uint32_t)(D_Z2BP + srow*72 + n0 + 2*tg)*4u, peer);
                float2 ownv = rank ? make_float2(zacc[2], zacc[3])
                                   : make_float2(zacc[0], zacc[1]);
                int col = h*HFF + n0 + 2*tg;
                size_t ridx = (size_t)(b*LL + n*CSS + srow)*CC + col;
                *(float2*)&g_Z2b[ridx] =
                    make_float2(to_tf32(ownv.x + pv.x), to_tf32(ownv.y + pv.y));
            }
            const float cl = sCo[15];
            const int m0 = w*16;
            float wa[8][4];
#pragma unroll
            for (int i=0;i<8;i++)
#pragma unroll
                for (int q=0;q<4;q++) wa[i][q]=0.f;
#pragma unroll
            for (int ks=0; ks<2; ks++){
                int k0 = ks*8;
                uint32_t ah[4],al[4];
                ldAfT2(sZ1h, sZ1l, 132, m0, k0, lane, ah, al);
#pragma unroll
                for (int nf=0; nf<8; nf++){
                    uint32_t bhf[2], blf[2];
                    ldBf2(sG2h, sG2l, 72, k0, nf*8, lane, bhf, blf);
                    mma3(wa[nf], ah, al, bhf, blf);
                }
            }
#pragma unroll
            for (int nf=0; nf<8; nf++){
                int col = nf*8 + 2*tg;
                float2 h0 = *(float2*)&sW2h[(m0+g)*72 + col];
                float2 l0 = *(float2*)&sW2l[(m0+g)*72 + col];
                float2 h1 = *(float2*)&sW2h[(m0+g+8)*72 + col];
                float2 l1 = *(float2*)&sW2l[(m0+g+8)*72 + col];
                float2 sa = sp(h0.x + l0.x - cl*wa[nf][0]);
                float2 sb = sp(h0.y + l0.y - cl*wa[nf][1]);
                float2 sc = sp(h1.x + l1.x - cl*wa[nf][2]);
                float2 sd = sp(h1.y + l1.y - cl*wa[nf][3]);
                *(float2*)&sW2h[(m0+g)*72 + col]   = make_float2(sa.x, sb.x);
                *(float2*)&sW2l[(m0+g)*72 + col]   = make_float2(sa.y, sb.y);
                *(float2*)&sW2h[(m0+g+8)*72 + col] = make_float2(sc.x, sd.x);
                *(float2*)&sW2l[(m0+g+8)*72 + col] = make_float2(sc.y, sd.y);
            }
        }
        __syncthreads();
    }
    CLUSTER_SYNC();
}

// ---------------- launch -----------------
extern "C" void kernel_launch(void* const* d_in, const int* in_sizes, int n_in,
                              void* d_out, int out_size)
{
    const float* hs  = (const float*)d_in[0];
    const float* Wq  = (const float*)d_in[1];
    const float* Wk  = (const float*)d_in[2];
    const float* Wv  = (const float*)d_in[3];
    const float* Wo  = (const float*)d_in[4];
    const float* ilw = (const float*)d_in[5];
    const float* ilb = (const float*)d_in[6];
    const float* W1  = (const float*)d_in[7];
    const float* W2  = (const float*)d_in[8];
    float* out = (float*)d_out;

    cudaFuncSetAttribute(scan_kernel, cudaFuncAttributeMaxDynamicSharedMemorySize,
                         SCAN_SMEM_BYTES);

    void *pX, *pZ2b, *pHsr, *pWT;
    cudaGetSymbolAddress(&pX, g_X);
    cudaGetSymbolAddress(&pZ2b, g_Z2b);
    cudaGetSymbolAddress(&pHsr, g_hsr);
    cudaGetSymbolAddress(&pWT, g_WT);
    float* hsr = (float*)pHsr;
    float* WT  = (float*)pWT;

    // launch 1: round
    round_kernel<<<(size_t)MROWS*CC/4/256, 256>>>(hs, hsr);
    // launch 2: transposes + ilr fused
    transpose3i_kernel<<<dim3(32,32,4), 256>>>(Wq, Wk, Wv, WT, hs, ilw, ilb);
    // launch 3: fused QKV GEMM
    dim3 gq(3*CC/128, MROWS/128);
    gemm_tf32<1><<<gq, 256>>>(hsr, WT, (float*)pX);
    // launch 4: scan (ncu capture slot)
    scan_kernel<<<BB*NHH*2, 256, SCAN_SMEM_BYTES>>>(W1, W2);
    // launch 5-6: Wo transpose + output GEMM
    transpose_kernel<<<dim3(32,32), 256>>>(Wo, WT + 3*(size_t)CC*CC);
    dim3 go(CC/128, MROWS/128);
    gemm_tf32<0><<<go, 256>>>((const float*)pZ2b, WT + 3*(size_t)CC*CC, out);
}

// round 16
// speedup vs baseline: 1.1286x; 1.0088x over previous
#include <cuda_runtime.h>
#include <math.h>
#include <stdint.h>

#define BB 4
#define LL 4096
#define CC 1024
#define NHH 16
#define CSS 16
#define HFF 64
#define HF4 256
#define NCC 256
#define MROWS (BB*LL)   // 16384
#define XSZ (BB*NHH*NCC*CSS*HFF)

// ---------------- device scratch -----------------
__device__ float g_X[3*XSZ];                 // [0]=XC, [1]=XB, [2]=XA (split layout)
__device__ float g_coef[BB*NHH*NCC*CSS];
__device__ float g_Z2b[(size_t)MROWS*CC];
__device__ float g_hsr[(size_t)MROWS*CC];
__device__ float g_WT[4][CC*CC];

// ---------------- helpers -----------------
__device__ __forceinline__ float to_tf32(float x){
    uint32_t u; asm("cvt.rna.tf32.f32 %0, %1;" : "=r"(u) : "f"(x));
    return __uint_as_float(u);
}
__device__ __forceinline__ uint32_t f2tf(float x){
    uint32_t u; asm("cvt.rna.tf32.f32 %0, %1;" : "=r"(u) : "f"(x));
    return u;
}
__device__ __forceinline__ void splitf(float v, uint32_t& h, uint32_t& l){
    h = f2tf(v);
    l = f2tf(v - __uint_as_float(h));
}
__device__ __forceinline__ float2 sp(float v){
    uint32_t h,l; splitf(v,h,l);
    return make_float2(__uint_as_float(h), __uint_as_float(l));
}
__device__ __forceinline__ uint32_t fu(float x){ return __float_as_uint(x); }
__device__ __forceinline__ void ldsm4(uint32_t* r, uint32_t addr){
    asm volatile("ldmatrix.sync.aligned.m8n8.x4.shared.b16 {%0,%1,%2,%3}, [%4];"
        : "=r"(r[0]),"=r"(r[1]),"=r"(r[2]),"=r"(r[3]) : "r"(addr));
}
__device__ __forceinline__ void mma_tf32(float* c, const uint32_t* a, uint32_t b0, uint32_t b1){
    asm volatile("mma.sync.aligned.m16n8k8.row.col.f32.tf32.tf32.f32 "
        "{%0,%1,%2,%3},{%4,%5,%6,%7},{%8,%9},{%0,%1,%2,%3};"
        : "+f"(c[0]),"+f"(c[1]),"+f"(c[2]),"+f"(c[3])
        : "r"(a[0]),"r"(a[1]),"r"(a[2]),"r"(a[3]),"r"(b0),"r"(b1));
}
__device__ __forceinline__ void mma3(float* c, const uint32_t* ah, const uint32_t* al,
                                     const uint32_t* bh, const uint32_t* bl){
    mma_tf32(c, ah, bh[0], bh[1]);
    mma_tf32(c, ah, bl[0], bl[1]);
    mma_tf32(c, al, bh[0], bh[1]);
}
// raw split-at-consume loader (W1 only)
__device__ __forceinline__ void ldBf(const float* S, int ld, int k0, int n0, int lane,
                                     uint32_t* bh, uint32_t* bl){
    int g = lane >> 2, tg = lane & 3;
    splitf(S[(k0+tg)*ld + n0+g],   bh[0], bl[0]);
    splitf(S[(k0+tg+4)*ld + n0+g], bh[1], bl[1]);
}
// twin-array scalar loaders (pre-split) - used where ldsm not applicable
__device__ __forceinline__ void ldAf2(const float* Sh, const float* Sl, int ld, int k0,
                                      int lane, uint32_t* ah, uint32_t* al){
    int g = lane >> 2, tg = lane & 3;
    ah[0]=fu(Sh[g*ld + k0+tg]);       al[0]=fu(Sl[g*ld + k0+tg]);
    ah[1]=fu(Sh[(g+8)*ld + k0+tg]);   al[1]=fu(Sl[(g+8)*ld + k0+tg]);
    ah[2]=fu(Sh[g*ld + k0+tg+4]);     al[2]=fu(Sl[g*ld + k0+tg+4]);
    ah[3]=fu(Sh[(g+8)*ld + k0+tg+4]); al[3]=fu(Sl[(g+8)*ld + k0+tg+4]);
}
__device__ __forceinline__ void ldAfT2(const float* Sh, const float* Sl, int ld, int m0,
                                       int k0, int lane, uint32_t* ah, uint32_t* al){
    int g = lane >> 2, tg = lane & 3;
    ah[0]=fu(Sh[(k0+tg)*ld + m0+g]);     al[0]=fu(Sl[(k0+tg)*ld + m0+g]);
    ah[1]=fu(Sh[(k0+tg)*ld + m0+g+8]);   al[1]=fu(Sl[(k0+tg)*ld + m0+g+8]);
    ah[2]=fu(Sh[(k0+tg+4)*ld + m0+g]);   al[2]=fu(Sl[(k0+tg+4)*ld + m0+g]);
    ah[3]=fu(Sh[(k0+tg+4)*ld + m0+g+8]); al[3]=fu(Sl[(k0+tg+4)*ld + m0+g+8]);
}
__device__ __forceinline__ void ldBf2(const float* Sh, const float* Sl, int ld, int k0,
                                      int n0, int lane, uint32_t* bh, uint32_t* bl){
    int g = lane >> 2, tg = lane & 3;
    bh[0]=fu(Sh[(k0+tg)*ld + n0+g]);   bl[0]=fu(Sl[(k0+tg)*ld + n0+g]);
    bh[1]=fu(Sh[(k0+tg+4)*ld + n0+g]); bl[1]=fu(Sl[(k0+tg+4)*ld + n0+g]);
}
__device__ __forceinline__ void ldBfT2(const float* Sh, const float* Sl, int ld, int k0,
                                       int n0, int lane, uint32_t* bh, uint32_t* bl){
    int g = lane >> 2, tg = lane & 3;
    bh[0]=fu(Sh[(n0+g)*ld + k0+tg]);   bl[0]=fu(Sl[(n0+g)*ld + k0+tg]);
    bh[1]=fu(Sh[(n0+g)*ld + k0+tg+4]); bl[1]=fu(Sl[(n0+g)*ld + k0+tg+4]);
}

// ---------------- cluster helpers -----------------
#define CLUSTER_SYNC() do{ \
    asm volatile("barrier.cluster.arrive.aligned;" ::: "memory"); \
    asm volatile("barrier.cluster.wait.aligned;"   ::: "memory"); }while(0)

__device__ __forceinline__ uint32_t mapa_u32(uint32_t laddr, uint32_t rank){
    uint32_t ra; asm("mapa.shared::cluster.u32 %0, %1, %2;" : "=r"(ra) : "r"(laddr), "r"(rank));
    return ra;
}
__device__ __forceinline__ float4 peer_f4(uint32_t laddr, uint32_t peer){
    uint32_t ra = mapa_u32(laddr, peer);
    float4 v;
    asm volatile("ld.shared::cluster.v4.f32 {%0,%1,%2,%3}, [%4];"
        : "=f"(v.x),"=f"(v.y),"=f"(v.z),"=f"(v.w) : "r"(ra));
    return v;
}
__device__ __forceinline__ float2 peer_f2(uint32_t laddr, uint32_t peer){
    uint32_t ra = mapa_u32(laddr, peer);
    float2 v;
    asm volatile("ld.shared::cluster.v2.f32 {%0,%1}, [%2];"
        : "=f"(v.x),"=f"(v.y) : "r"(ra));
    return v;
}
__device__ __forceinline__ float peer_f1(uint32_t laddr, uint32_t peer){
    uint32_t ra = mapa_u32(laddr, peer);
    float v;
    asm volatile("ld.shared::cluster.f32 %0, [%1];" : "=f"(v) : "r"(ra));
    return v;
}

// ---------------- prep kernels -----------------
__global__ void __launch_bounds__(256) round_kernel(const float* __restrict__ in,
                                                    float* __restrict__ out){
    size_t i = (size_t)blockIdx.x*256 + threadIdx.x;
    float4 v = ((const float4*)in)[i];
    ((float4*)out)[i] = make_float4(to_tf32(v.x), to_tf32(v.y), to_tf32(v.z), to_tf32(v.w));
}
__global__ void __launch_bounds__(256) transpose3i_kernel(const float* __restrict__ Wq,
                                                          const float* __restrict__ Wk,
                                                          const float* __restrict__ Wv,
                                                          float* __restrict__ out,
                                                          const float* __restrict__ hs,
                                                          const float* __restrict__ ilw,
                                                          const float* __restrict__ ilb){
    if (blockIdx.z < 3){
        __shared__ float tile[32][33];
        const float* in = (blockIdx.z==0) ? Wq : (blockIdx.z==1) ? Wk : Wv;
        float* o = out + (size_t)blockIdx.z*CC*CC;
        int bx = blockIdx.x*32, by = blockIdx.y*32;
        int tx = threadIdx.x & 31, ty = threadIdx.x >> 5;
        for (int r = ty; r < 32; r += 8)
            tile[r][tx] = in[(size_t)(by+r)*CC + bx + tx];
        __syncthreads();
        for (int r = ty; r < 32; r += 8)
            o[(size_t)(bx+r)*CC + by + tx] = to_tf32(tile[tx][r]);
    } else {
        int blk = blockIdx.y*32 + blockIdx.x;
        int h = threadIdx.x & 15, rloc = threadIdx.x >> 4;
        int row = blk*16 + rloc;
        const float* hp = hs + (size_t)row*CC;
        float a0=0.f,a1=0.f,a2=0.f,a3=0.f;
        for (int k=0;k<CC;k+=4){
            float4 x = *(const float4*)(hp + k);
            a0 += x.x*ilw[(k+0)*NHH+h];
            a1 += x.y*ilw[(k+1)*NHH+h];
            a2 += x.z*ilw[(k+2)*NHH+h];
            a3 += x.w*ilw[(k+3)*NHH+h];
        }
        float acc = (a0+a1)+(a2+a3) + ilb[h];
        float sig = 1.f/(1.f+expf(-acc));
        int b = row>>12, l = row&4095, n = l>>4, s = l&15;
        g_coef[((size_t)(b*NHH+h)*NCC+n)*CSS+s] = sig*(1.f/(float)(s+1))*(1.f/(float)HFF);
    }
}
__global__ void __launch_bounds__(256) transpose_kernel(const float* __restrict__ in,
                                                        float* __restrict__ out){
    __shared__ float tile[32][33];
    int bx = blockIdx.x*32, by = blockIdx.y*32;
    int tx = threadIdx.x & 31, ty = threadIdx.x >> 5;
    for (int r = ty; r < 32; r += 8)
        tile[r][tx] = in[(size_t)(by+r)*CC + bx + tx];
    __syncthreads();
    for (int r = ty; r < 32; r += 8)
        out[(size_t)(bx+r)*CC + by + tx] = to_tf32(tile[tx][r]);
}

// ---------------- tf32 GEMM (unchanged) --------------------------------------
#define GPAD 36
template<int SPLIT>
__global__ void __launch_bounds__(256) gemm_tf32(const float* __restrict__ A,
                                                 const float* __restrict__ BT,
                                                 float* __restrict__ out)
{
    __shared__ float As[128*GPAD];
    __shared__ float Bs[128*GPAD];
    const int t = threadIdx.x, lane = t & 31, warp = t >> 5;
    const int wm = warp >> 1, wn = warp & 1;
    const int bm = blockIdx.y, bn = blockIdx.x;

    float acc[2][8][4];
#pragma unroll
    for (int i=0;i<2;i++)
#pragma unroll
        for (int j=0;j<8;j++)
#pragma unroll
            for (int q=0;q<4;q++) acc[i][j][q]=0.f;

    const uint32_t As_u = (uint32_t)__cvta_generic_to_shared(As);
    const uint32_t Bs_u = (uint32_t)__cvta_generic_to_shared(Bs);
    uint32_t a_addr[2], b_addr[4];
#pragma unroll
    for (int mf=0; mf<2; mf++){
        int row = wm*32 + mf*16 + (lane & 15);
        a_addr[mf] = As_u + (uint32_t)(row*GPAD + (lane>>4)*4)*4u;
    }
#pragma unroll
    for (int nf2=0; nf2<4; nf2++){
        int nr = wn*64 + nf2*16 + (lane & 7) + ((lane>>4)&1)*8;
        b_addr[nf2] = Bs_u + (uint32_t)(nr*GPAD + ((lane>>3)&1)*4)*4u;
    }

    const float* Ab  = A  + (size_t)(bm*128)*CC;
    const float* BTb = BT + (size_t)(bn*128)*CC;
    const int row = t >> 3, k4 = (t & 7)*4;

    float4 ar[4], br[4];
#pragma unroll
    for (int i=0;i<4;i++){
        int r = row + i*32;
        ar[i] = *(const float4*)(Ab  + (size_t)r*CC + k4);
        br[i] = *(const float4*)(BTb + (size_t)r*CC + k4);
    }

    for (int it=0; it<32; it++){
        __syncthreads();
#pragma unroll
        for (int i=0;i<4;i++){
            int r = row + i*32;
            *(float4*)&As[r*GPAD + k4] = ar[i];
            *(float4*)&Bs[r*GPAD + k4] = br[i];
        }
        __syncthreads();
        if (it < 31){
            const int kb = (it+1)*32;
#pragma unroll
            for (int i=0;i<4;i++){
                int r = row + i*32;
                ar[i] = *(const float4*)(Ab  + (size_t)r*CC + kb + k4);
                br[i] = *(const float4*)(BTb + (size_t)r*CC + kb + k4);
            }
        }
#pragma unroll
        for (int s8=0; s8<4; s8++){
            uint32_t a[2][4], bf[4][4];
            ldsm4(a[0], a_addr[0] + s8*32);
            ldsm4(a[1], a_addr[1] + s8*32);
            ldsm4(bf[0], b_addr[0] + s8*32);
            ldsm4(bf[1], b_addr[1] + s8*32);
            ldsm4(bf[2], b_addr[2] + s8*32);
            ldsm4(bf[3], b_addr[3] + s8*32);
#pragma unroll
            for (int nf=0; nf<8; nf++){
                uint32_t b0 = bf[nf>>1][(nf&1)*2], b1 = bf[nf>>1][(nf&1)*2+1];
                mma_tf32(acc[0][nf], a[0], b0, b1);
                mma_tf32(acc[1][nf], a[1], b0, b1);
            }
        }
    }

#pragma unroll
    for (int mf=0; mf<2; mf++){
#pragma unroll
        for (int nf=0; nf<8; nf++){
            int r = bm*128 + wm*32 + mf*16 + (lane>>2);
            int c = bn*128 + wn*64 + nf*8 + (lane&3)*2;
#pragma unroll
            for (int half=0; half<2; half++){
                int rr = r + half*8;
                float2 v = make_float2(acc[mf][nf][half*2], acc[mf][nf][half*2+1]);
                if (SPLIT){
                    int proj = c >> 10, cc = c & 1023;
                    int b = rr >> 12, l = rr & 4095;
                    int n = l >> 4, s = l & 15;
                    int h = cc >> 6, f = cc & 63;
                    size_t idx = (size_t)proj*XSZ +
                                 ((((size_t)(b*NHH + h)*NCC + n)*CSS + s)*HFF + f);
                    *(float2*)(out + idx) = v;
                } else {
                    *(float2*)(out + (size_t)rr*CC + c) = v;
                }
            }
        }
    }
}

// ---------------- TTT scan: twin caches + ldsm A-frags + prefetch ------------
#define D_W1    0                        // raw 64x132
#define D_W2H   (D_W1 + 64*132)
#define D_W2L   (D_W2H + 128*72)
#define D_XA    (D_W2L + 128*72)         // raw 16x68
#define D_XBH   (D_XA + 16*68)
#define D_XBL   (D_XBH + 16*68)
#define D_XCH   (D_XBL + 16*68)
#define D_XCL   (D_XCH + 16*68)
#define D_Z1H   (D_XCL + 16*68)          // 16x132
#define D_Z1L   (D_Z1H + 16*132)
#define D_Z1BH  (D_Z1L + 16*132)
#define D_Z1BL  (D_Z1BH + 16*132)
#define D_G1H   (D_Z1BL + 16*132)
#define D_G1L   (D_G1H + 16*132)
#define D_G2H   (D_G1L + 16*132)         // 16x68 (stride 68: ldsm conflict-free)
#define D_G2L   (D_G2H + 16*68)
#define D_Z2P   (D_G2L + 16*68)          // raw 16x72 (DSMEM)
#define D_Z2BP  (D_Z2P + 16*72)          // raw 16x72 (DSMEM)
#define D_A1MH  (D_Z2BP + 16*72)         // 16x20
#define D_A1ML  (D_A1MH + 16*20)
#define D_A2MH  (D_A1ML + 16*20)
#define D_A2ML  (D_A2MH + 16*20)
#define D_A2P   (D_A2ML + 16*20)         // raw 16x20 (DSMEM)
#define D_ST    (D_A2P + 16*20)          // 8x16x18
#define D_CO    (D_ST + 8*16*18)
#define SCAN_SMEM_FLOATS (D_CO + 16)
#define SCAN_SMEM_BYTES  (SCAN_SMEM_FLOATS*4)

__global__ void __launch_bounds__(256,1) __cluster_dims__(2,1,1)
scan_kernel(const float* __restrict__ W1g, const float* __restrict__ W2g)
{
    extern __shared__ float sm[];
    float* sW1   = sm + D_W1;
    float* sW2h  = sm + D_W2H;
    float* sW2l  = sm + D_W2L;
    float* sXA   = sm + D_XA;
    float* sXBh  = sm + D_XBH;
    float* sXBl  = sm + D_XBL;
    float* sXCh  = sm + D_XCH;
    float* sXCl  = sm + D_XCL;
    float* sZ1h  = sm + D_Z1H;
    float* sZ1l  = sm + D_Z1L;
    float* sZ1bh = sm + D_Z1BH;
    float* sZ1bl = sm + D_Z1BL;
    float* sG1h  = sm + D_G1H;
    float* sG1l  = sm + D_G1L;
    float* sG2h  = sm + D_G2H;
    float* sG2l  = sm + D_G2L;
    float* sZ2p  = sm + D_Z2P;
    float* sZ2bp = sm + D_Z2BP;
    float* sA1mh = sm + D_A1MH;
    float* sA1ml = sm + D_A1ML;
    float* sA2mh = sm + D_A2MH;
    float* sA2ml = sm + D_A2ML;
    float* sA2p  = sm + D_A2P;
    float* sSt   = sm + D_ST;
    float* sCo   = sm + D_CO;

    const int t = threadIdx.x;
    const int lane = t & 31, w = t >> 5;
    const int g = lane >> 2, tg = lane & 3;
    uint32_t rank; asm("mov.u32 %0, %%cluster_ctarank;" : "=r"(rank));
    const uint32_t peer = rank ^ 1u;
    const int bh = blockIdx.x >> 1;
    const int b  = bh >> 4, h = bh & 15;
    const uint32_t smb = (uint32_t)__cvta_generic_to_shared(sm);

    // ldsm base addresses (rows = lane&15, col-group = (lane>>4)*4)
    const int l15 = lane & 15, lh4 = (lane >> 4)*4;
    const uint32_t adXBh = smb + (uint32_t)(D_XBH + l15*68 + lh4)*4u;
    const uint32_t adXBl = smb + (uint32_t)(D_XBL + l15*68 + lh4)*4u;
    const uint32_t adXCh = smb + (uint32_t)(D_XCH + l15*68 + lh4)*4u;
    const uint32_t adXCl = smb + (uint32_t)(D_XCL + l15*68 + lh4)*4u;
    const uint32_t adZ1h = smb + (uint32_t)(D_Z1H + l15*132 + lh4)*4u;
    const uint32_t adZ1l = smb + (uint32_t)(D_Z1L + l15*132 + lh4)*4u;
    const uint32_t adZ1bh= smb + (uint32_t)(D_Z1BH + l15*132 + lh4)*4u;
    const uint32_t adZ1bl= smb + (uint32_t)(D_Z1BL + l15*132 + lh4)*4u;
    const uint32_t adG2h = smb + (uint32_t)(D_G2H + l15*68 + lh4)*4u;
    const uint32_t adG2l = smb + (uint32_t)(D_G2L + l15*68 + lh4)*4u;

    const float* w1p = W1g + (size_t)h*HFF*HF4;
    for (int i = t; i < HFF*128; i += 256)
        sW1[(i>>7)*132 + (i&127)] = w1p[(size_t)(i>>7)*HF4 + rank*128 + (i&127)];
    const float* w2p = W2g + (size_t)h*HF4*HFF;
    for (int i = t; i < 128*HFF; i += 256){
        int k = i>>6, f = i&63;
        float2 v = sp(w2p[(size_t)(rank*128 + k)*HFF + f]);
        sW2h[k*72 + f] = v.x;
        sW2l[k*72 + f] = v.y;
    }

    const size_t cbase = (size_t)bh * (NCC*CSS*HFF);
    const float* gXC = g_X;
    const float* gXB = g_X + XSZ;
    const float* gXA = g_X + 2*(size_t)XSZ;

    // prefetch chunk 0 into registers
    float4 pfa, pfb, pfc;
    float pfco = 0.f;
    pfa = ((const float4*)(gXA + cbase))[t];
    pfb = ((const float4*)(gXB + cbase))[t];
    pfc = ((const float4*)(gXC + cbase))[t];
    if (t < 16) pfco = g_coef[(size_t)bh*(NCC*CSS) + t];

    for (int n = 0; n < NCC; n++) {
        // ---- store prefetched chunk to smem (split XB/XC) ----
        {
            int e = t*4, s = e >> 6, f = e & 63;
            *(float4*)(sXA + s*68 + f) = pfa;
            float2 b0=sp(pfb.x), b1=sp(pfb.y), b2=sp(pfb.z), b3=sp(pfb.w);
            *(float4*)&sXBh[s*68 + f] = make_float4(b0.x,b1.x,b2.x,b3.x);
            *(float4*)&sXBl[s*68 + f] = make_float4(b0.y,b1.y,b2.y,b3.y);
            float2 c0=sp(pfc.x), c1_=sp(pfc.y), c2=sp(pfc.z), c3=sp(pfc.w);
            *(float4*)&sXCh[s*68 + f] = make_float4(c0.x,c1_.x,c2.x,c3.x);
            *(float4*)&sXCl[s*68 + f] = make_float4(c0.y,c1_.y,c2.y,c3.y);
            if (t < 16) sCo[t] = pfco;
        }
        __syncthreads();
        if (n+1 < NCC){
            const size_t off = cbase + (size_t)(n+1)*1024;
            pfa = ((const float4*)(gXA + off))[t];
            pfb = ((const float4*)(gXB + off))[t];
            pfc = ((const float4*)(gXC + off))[t];
            if (t < 16) pfco = g_coef[(size_t)bh*(NCC*CSS) + (n+1)*CSS + t];
        }

        // ---- P1: Z1loc = XB@W1loc ; Ploc = XC@W1loc (ldsm A) ----
        {
            const int n0 = w*16;
            float aZ[2][4], aP[2][4];
#pragma unroll
            for (int i=0;i<2;i++)
#pragma unroll
                for (int q=0;q<4;q++){ aZ[i][q]=0.f; aP[i][q]=0.f; }
#pragma unroll
            for (int ks=0; ks<8; ks++){
                int k0 = ks*8;
                uint32_t aBh[4],aBl[4],aCh[4],aCl[4];
                ldsm4(aBh, adXBh + k0*4);
                ldsm4(aBl, adXBl + k0*4);
                ldsm4(aCh, adXCh + k0*4);
                ldsm4(aCl, adXCl + k0*4);
#pragma unroll
                for (int nf=0; nf<2; nf++){
                    uint32_t bhf[2], blf[2];
                    ldBf(sW1, 132, k0, n0+nf*8, lane, bhf, blf);
                    mma3(aZ[nf], aBh, aBl, bhf, blf);
                    mma3(aP[nf], aCh, aCl, bhf, blf);
                }
            }
#pragma unroll
            for (int nf=0; nf<2; nf++){
                int col = n0 + nf*8 + 2*tg;
                float2 z0=sp(aZ[nf][0]), z1=sp(aZ[nf][1]), z2=sp(aZ[nf][2]), z3=sp(aZ[nf][3]);
                *(float2*)&sZ1h[g*132 + col]     = make_float2(z0.x, z1.x);
                *(float2*)&sZ1l[g*132 + col]     = make_float2(z0.y, z1.y);
                *(float2*)&sZ1h[(g+8)*132 + col] = make_float2(z2.x, z3.x);
                *(float2*)&sZ1l[(g+8)*132 + col] = make_float2(z2.y, z3.y);
                float2 p0=sp(aP[nf][0]), p1=sp(aP[nf][1]), p2=sp(aP[nf][2]), p3=sp(aP[nf][3]);
                *(float2*)&sZ1bh[g*132 + col]     = make_float2(p0.x, p1.x);
                *(float2*)&sZ1bl[g*132 + col]     = make_float2(p0.y, p1.y);
                *(float2*)&sZ1bh[(g+8)*132 + col] = make_float2(p2.x, p3.x);
                *(float2*)&sZ1bl[(g+8)*132 + col] = make_float2(p2.y, p3.y);
            }
        }
        __syncthreads();

        // ---- P2: Z2 partial (ldsm A from Z1) ; warps 0,1: A1m (ldsm XC) ----
        {
            const int n0 = w*8;
            float acc[4] = {0.f,0.f,0.f,0.f};
#pragma unroll 4
            for (int ks=0; ks<16; ks++){
                int k0 = ks*8;
                uint32_t ah[4],al[4],bhf[2],blf[2];
                ldsm4(ah, adZ1h + k0*4);
                ldsm4(al, adZ1l + k0*4);
                ldBf2(sW2h, sW2l, 72, k0, n0, lane, bhf, blf);
                mma3(acc, ah, al, bhf, blf);
            }
            {
                int col = n0 + 2*tg;
                *(float2*)&sZ2p[g*72 + col]     = make_float2(acc[0], acc[1]);
                *(float2*)&sZ2p[(g+8)*72 + col] = make_float2(acc[2], acc[3]);
            }
            if (w < 2){
                const int an0 = w*8;
                float a1[4] = {0.f,0.f,0.f,0.f};
#pragma unroll
                for (int ks=0; ks<8; ks++){
                    int k0 = ks*8;
                    uint32_t ah[4],al[4],bhf[2],blf[2];
                    ldsm4(ah, adXCh + k0*4);
                    ldsm4(al, adXCl + k0*4);
                    ldBfT2(sXBh, sXBl, 68, k0, an0, lane, bhf, blf);
                    mma3(a1, ah, al, bhf, blf);
                }
                int u0 = an0 + 2*tg;
                int s0 = g, s1 = g+8;
                float2 q;
                q = (u0   <= s0) ? sp(-sCo[s0]*a1[0]) : make_float2(0.f,0.f);
                sA1mh[s0*20 + u0] = q.x;   sA1ml[s0*20 + u0] = q.y;
                q = (u0+1 <= s0) ? sp(-sCo[s0]*a1[1]) : make_float2(0.f,0.f);
                sA1mh[s0*20 + u0+1] = q.x; sA1ml[s0*20 + u0+1] = q.y;
                q = (u0   <= s1) ? sp(-sCo[s1]*a1[2]) : make_float2(0.f,0.f);
                sA1mh[s1*20 + u0] = q.x;   sA1ml[s1*20 + u0] = q.y;
                q = (u0+1 <= s1) ? sp(-sCo[s1]*a1[3]) : make_float2(0.f,0.f);
                sA1mh[s1*20 + u0+1] = q.x; sA1ml[s1*20 + u0+1] = q.y;
            }
        }
        CLUSTER_SYNC();

        // ---- g2 = Z2p_own + Z2p_peer - XA -> twin stores (stride 68) ----
        {
            int row = t >> 4, c4 = (t & 15)*4;
            float4 own = *(float4*)&sZ2p[row*72 + c4];
            float4 pv  = peer_f4(smb + (uint32_t)(D_Z2P + row*72 + c4)*4u, peer);
            float4 xa  = *(float4*)&sXA[row*68 + c4];
            float2 g0 = sp(own.x+pv.x-xa.x), g1_ = sp(own.y+pv.y-xa.y);
            float2 g2_ = sp(own.z+pv.z-xa.z), g3 = sp(own.w+pv.w-xa.w);
            *(float4*)&sG2h[row*68 + c4] = make_float4(g0.x,g1_.x,g2_.x,g3.x);
            *(float4*)&sG2l[row*68 + c4] = make_float4(g0.y,g1_.y,g2_.y,g3.y);
        }
        __syncthreads();

        // ---- P3: g1loc = g2 @ W2loc^T (ldsm A from G2) ----
        {
            const int n0 = w*16;
            float accG[2][4];
#pragma unroll
            for (int i=0;i<2;i++)
#pragma unroll
                for (int q=0;q<4;q++) accG[i][q]=0.f;
#pragma unroll
            for (int ks=0; ks<8; ks++){
                int k0 = ks*8;
                uint32_t ah[4],al[4];
                ldsm4(ah, adG2h + k0*4);
                ldsm4(al, adG2l + k0*4);
#pragma unroll
                for (int nf=0; nf<2; nf++){
                    uint32_t bhf[2], blf[2];
                    ldBfT2(sW2h, sW2l, 72, k0, n0+nf*8, lane, bhf, blf);
                    mma3(accG[nf], ah, al, bhf, blf);
                }
            }
#pragma unroll
            for (int nf=0; nf<2; nf++){
                int col = n0 + nf*8 + 2*tg;
                float2 q0=sp(accG[nf][0]), q1=sp(accG[nf][1]), q2=sp(accG[nf][2]), q3=sp(accG[nf][3]);
                *(float2*)&sG1h[g*132 + col]     = make_float2(q0.x, q1.x);
                *(float2*)&sG1l[g*132 + col]     = make_float2(q0.y, q1.y);
                *(float2*)&sG1h[(g+8)*132 + col] = make_float2(q2.x, q3.x);
                *(float2*)&sG1l[(g+8)*132 + col] = make_float2(q2.y, q3.y);
            }
        }
        __syncthreads();

        // ---- P4: Z1b += A1m@g1loc ; W1 -= cl*(XB^T@g1loc) ----
        {
            const int n0 = w*16;
            float c1[2][4];
#pragma unroll
            for (int i=0;i<2;i++)
#pragma unroll
                for (int q=0;q<4;q++) c1[i][q]=0.f;
#pragma unroll
            for (int ks=0; ks<2; ks++){
                int k0 = ks*8;
                uint32_t ah[4],al[4];
                ldAf2(sA1mh, sA1ml, 20, k0, lane, ah, al);
#pragma unroll
                for (int nf=0; nf<2; nf++){
                    uint32_t bhf[2], blf[2];
                    ldBf2(sG1h, sG1l, 132, k0, n0+nf*8, lane, bhf, blf);
                    mma3(c1[nf], ah, al, bhf, blf);
                }
            }
#pragma unroll
            for (int nf=0; nf<2; nf++){
                int col = n0 + nf*8 + 2*tg;
                float2 h0 = *(float2*)&sZ1bh[g*132 + col];
                float2 l0 = *(float2*)&sZ1bl[g*132 + col];
                float2 h1 = *(float2*)&sZ1bh[(g+8)*132 + col];
                float2 l1 = *(float2*)&sZ1bl[(g+8)*132 + col];
                float2 s00 = sp(h0.x + l0.x + c1[nf][0]);
                float2 s01 = sp(h0.y + l0.y + c1[nf][1]);
                float2 s10 = sp(h1.x + l1.x + c1[nf][2]);
                float2 s11 = sp(h1.y + l1.y + c1[nf][3]);
                *(float2*)&sZ1bh[g*132 + col]     = make_float2(s00.x, s01.x);
                *(float2*)&sZ1bl[g*132 + col]     = make_float2(s00.y, s01.y);
                *(float2*)&sZ1bh[(g+8)*132 + col] = make_float2(s10.x, s11.x);
                *(float2*)&sZ1bl[(g+8)*132 + col] = make_float2(s10.y, s11.y);
            }
            const float cl = sCo[15];
            const int m0 = (w>>1)*16, nbase = (w&1)*64;
            float wa[8][4];
#pragma unroll
            for (int i=0;i<8;i++)
#pragma unroll
                for (int q=0;q<4;q++) wa[i][q]=0.f;
#pragma unroll
            for (int ks=0; ks<2; ks++){
                int k0 = ks*8;
                uint32_t ah[4],al[4];
                ldAfT2(sXBh, sXBl, 68, m0, k0, lane, ah, al);
#pragma unroll
                for (int nf=0; nf<8; nf++){
                    uint32_t bhf[2], blf[2];
                    ldBf2(sG1h, sG1l, 132, k0, nbase + nf*8, lane, bhf, blf);
                    mma3(wa[nf], ah, al, bhf, blf);
                }
            }
#pragma unroll
            for (int nf=0; nf<8; nf++){
                int col = nbase + nf*8 + 2*tg;
                float2 v0 = *(float2*)&sW1[(m0+g)*132 + col];
                float2 v1 = *(float2*)&sW1[(m0+g+8)*132 + col];
                v0.x -= cl*wa[nf][0]; v0.y -= cl*wa[nf][1];
                v1.x -= cl*wa[nf][2]; v1.y -= cl*wa[nf][3];
                *(float2*)&sW1[(m0+g)*132 + col]   = v0;
                *(float2*)&sW1[(m0+g+8)*132 + col] = v1;
            }
        }
        __syncthreads();

        // ---- P5: Z2b partial (ldsm A Z1b) ; A2 partial (ldsm A Z1b) ----
        float zacc[4] = {0.f,0.f,0.f,0.f};
        {
            const int n0 = w*8;
#pragma unroll 4
            for (int ks=0; ks<16; ks++){
                int k0 = ks*8;
                uint32_t ah[4],al[4],bhf[2],blf[2];
                ldsm4(ah, adZ1bh + k0*4);
                ldsm4(al, adZ1bl + k0*4);
                ldBf2(sW2h, sW2l, 72, k0, n0, lane, bhf, blf);
                mma3(zacc, ah, al, bhf, blf);
            }
            {
                int col = n0 + 2*tg;
                *(float2*)&sZ2bp[g*72 + col]     = make_float2(zacc[0], zacc[1]);
                *(float2*)&sZ2bp[(g+8)*72 + col] = make_float2(zacc[2], zacc[3]);
            }
            float pa[2][4];
#pragma unroll
            for (int i=0;i<2;i++)
#pragma unroll
                for (int q=0;q<4;q++) pa[i][q]=0.f;
            const int kb = w*16;
#pragma unroll
            for (int ks=0; ks<2; ks++){
                int k0 = kb + ks*8;
                uint32_t ah[4],al[4];
                ldsm4(ah, adZ1bh + k0*4);
                ldsm4(al, adZ1bl + k0*4);
#pragma unroll
                for (int nf=0; nf<2; nf++){
                    uint32_t bhf[2], blf[2];
                    ldBfT2(sZ1h, sZ1l, 132, k0, nf*8, lane, bhf, blf);
                    mma3(pa[nf], ah, al, bhf, blf);
                }
            }
#pragma unroll
            for (int nf=0; nf<2; nf++){
                int u = nf*8 + 2*tg;
                sSt[w*288 + g*18 + u]       = pa[nf][0];
                sSt[w*288 + g*18 + u+1]     = pa[nf][1];
                sSt[w*288 + (g+8)*18 + u]   = pa[nf][2];
                sSt[w*288 + (g+8)*18 + u+1] = pa[nf][3];
            }
        }
        __syncthreads();

        // ---- P5r: reduce staged A2 partials -> CTA partial (raw) ----
        {
            int s = t >> 4, u = t & 15;
            float sum = 0.f;
#pragma unroll
            for (int ww=0; ww<8; ww++) sum += sSt[ww*288 + s*18 + u];
            sA2p[s*20 + u] = sum;
        }
        CLUSTER_SYNC();

        // ---- A2m twins = split(-co*tril(A2_own + A2_peer)) ----
        {
            int s = t >> 4, u = t & 15;
            float pv = peer_f1(smb + (uint32_t)(D_A2P + s*20 + u)*4u, peer);
            float sum = sA2p[s*20 + u] + pv;
            float2 q = (u <= s) ? sp(-sCo[s]*sum) : make_float2(0.f,0.f);
            sA2mh[s*20 + u] = q.x;
            sA2ml[s*20 + u] = q.y;
        }
        __syncthreads();

        // ---- P6: corr2 ; combine + store ; W2 twin update ----
        {
            const int n0 = w*8;
#pragma unroll
            for (int ks=0; ks<2; ks++){
                int k0 = ks*8;
                uint32_t ah[4],al[4],bhf[2],blf[2];
                ldAf2(sA2mh, sA2ml, 20, k0, lane, ah, al);
                ldBf2(sG2h, sG2l, 68, k0, n0, lane, bhf, blf);
                mma3(zacc, ah, al, bhf, blf);
            }
            {
                int srow = rank ? (g+8) : g;
                float2 pv = peer_f2(smb + (uint32_t)(D_Z2BP + srow*72 + n0 + 2*tg)*4u, peer);
                float2 ownv = rank ? make_float2(zacc[2], zacc[3])
                                   : make_float2(zacc[0], zacc[1]);
                int col = h*HFF + n0 + 2*tg;
                size_t ridx = (size_t)(b*LL + n*CSS + srow)*CC + col;
                *(float2*)&g_Z2b[ridx] =
                    make_float2(to_tf32(ownv.x + pv.x), to_tf32(ownv.y + pv.y));
            }
            const float cl = sCo[15];
            const int m0 = w*16;
            float wa[8][4];
#pragma unroll
            for (int i=0;i<8;i++)
#pragma unroll
                for (int q=0;q<4;q++) wa[i][q]=0.f;
#pragma unroll
            for (int ks=0; ks<2; ks++){
                int k0 = ks*8;
                uint32_t ah[4],al[4];
                ldAfT2(sZ1h, sZ1l, 132, m0, k0, lane, ah, al);
#pragma unroll
                for (int nf=0; nf<8; nf++){
                    uint32_t bhf[2], blf[2];
                    ldBf2(sG2h, sG2l, 68, k0, nf*8, lane, bhf, blf);
                    mma3(wa[nf], ah, al, bhf, blf);
                }
            }
#pragma unroll
            for (int nf=0; nf<8; nf++){
                int col = nf*8 + 2*tg;
                float2 h0 = *(float2*)&sW2h[(m0+g)*72 + col];
                float2 l0 = *(float2*)&sW2l[(m0+g)*72 + col];
                float2 h1 = *(float2*)&sW2h[(m0+g+8)*72 + col];
                float2 l1 = *(float2*)&sW2l[(m0+g+8)*72 + col];
                float2 sa = sp(h0.x + l0.x - cl*wa[nf][0]);
                float2 sb = sp(h0.y + l0.y - cl*wa[nf][1]);
                float2 sc = sp(h1.x + l1.x - cl*wa[nf][2]);
                float2 sd = sp(h1.y + l1.y - cl*wa[nf][3]);
                *(float2*)&sW2h[(m0+g)*72 + col]   = make_float2(sa.x, sb.x);
                *(float2*)&sW2l[(m0+g)*72 + col]   = make_float2(sa.y, sb.y);
                *(float2*)&sW2h[(m0+g+8)*72 + col] = make_float2(sc.x, sd.x);
                *(float2*)&sW2l[(m0+g+8)*72 + col] = make_float2(sc.y, sd.y);
            }
        }
        __syncthreads();
    }
    CLUSTER_SYNC();
}

// ---------------- launch -----------------
extern "C" void kernel_launch(void* const* d_in, const int* in_sizes, int n_in,
                              void* d_out, int out_size)
{
    const float* hs  = (const float*)d_in[0];
    const float* Wq  = (const float*)d_in[1];
    const float* Wk  = (const float*)d_in[2];
    const float* Wv  = (const float*)d_in[3];
    const float* Wo  = (const float*)d_in[4];
    const float* ilw = (const float*)d_in[5];
    const float* ilb = (const float*)d_in[6];
    const float* W1  = (const float*)d_in[7];
    const float* W2  = (const float*)d_in[8];
    float* out = (float*)d_out;

    cudaFuncSetAttribute(scan_kernel, cudaFuncAttributeMaxDynamicSharedMemorySize,
                         SCAN_SMEM_BYTES);

    void *pX, *pZ2b, *pHsr, *pWT;
    cudaGetSymbolAddress(&pX, g_X);
    cudaGetSymbolAddress(&pZ2b, g_Z2b);
    cudaGetSymbolAddress(&pHsr, g_hsr);
    cudaGetSymbolAddress(&pWT, g_WT);
    float* hsr = (float*)pHsr;
    float* WT  = (float*)pWT;

    // launch 1: round
    round_kernel<<<(size_t)MROWS*CC/4/256, 256>>>(hs, hsr);
    // launch 2: transposes + ilr fused
    transpose3i_kernel<<<dim3(32,32,4), 256>>>(Wq, Wk, Wv, WT, hs, ilw, ilb);
    // launch 3: fused QKV GEMM
    dim3 gq(3*CC/128, MROWS/128);
    gemm_tf32<1><<<gq, 256>>>(hsr, WT, (float*)pX);
    // launch 4: scan (ncu capture slot)
    scan_kernel<<<BB*NHH*2, 256, SCAN_SMEM_BYTES>>>(W1, W2);
    // launch 5-6: Wo transpose + output GEMM
    transpose_kernel<<<dim3(32,32), 256>>>(Wo, WT + 3*(size_t)CC*CC);
    dim3 go(CC/128, MROWS/128);
    gemm_tf32<0><<<go, 256>>>((const float*)pZ2b, WT + 3*(size_t)CC*CC, out);
}